// round 9
// baseline (speedup 1.0000x reference)
#include <cuda_runtime.h>
#include <cuda_bf16.h>

// ---------------------------------------------------------------------------
// Problem constants
// ---------------------------------------------------------------------------
#define BB    128
#define PP    49
#define TT    20
#define NSTEP 19            // T-1 decode steps
#define HD    512
#define ENCD  2048
#define VOC   20000
#define MROWS (BB*PP)       // 6272
#define PRED_ELEMS (128LL*19LL*20000LL)   // 48,640,000

// ---------------------------------------------------------------------------
// Scratch (static device memory only; referenced ONLY from device code —
// kernel_launch performs no runtime API calls besides kernel launches, and
// NEVER references a __device__ symbol from host context)
// ---------------------------------------------------------------------------
__device__ __align__(128) float g_V   [MROWS*HD];       // relu(enc_s @ Wi^T + bi)
__device__ __align__(128) float g_WV  [MROWS*HD];       // V @ att_WV^T + bV
__device__ __align__(128) float g_X   [BB*NSTEP*1024];  // [emb | vg]
__device__ __align__(128) float g_Wpack[2560*1536];     // [W_ih|W_hh ; Wx|Wph]
__device__ __align__(128) float g_bpack[2560];
__device__ __align__(128) float g_CH  [NSTEP*BB*HD];    // c_hat + h_new per step
__device__ __align__(128) float g_G   [BB*2560];        // gates + gate-pre
__device__ __align__(128) float g_H   [BB*HD];          // masked recurrent h
__device__ __align__(128) float g_M   [BB*HD];          // masked recurrent m
__device__ __align__(128) float g_HN  [BB*HD];          // unmasked h_new
__device__ __align__(128) float g_S   [BB*HD];          // sentinel s
__device__ __align__(128) float g_WhWs[2*BB*HD];        // rows 0..127 Wh, 128..255 Ws
__device__ __align__(128) float g_vg  [BB*HD];
__device__ int g_sortind[BB];
__device__ int g_declen [BB];     // sorted descending
__device__ int g_cnt    [NSTEP];  // # active rows at step t
__device__ int g_capss  [BB*TT];

// ---------------------------------------------------------------------------
// f32x2 helpers (FFMA2 — 2x fp32 FMA rate on sm_103a, only reachable via PTX)
// ---------------------------------------------------------------------------
__device__ __forceinline__ unsigned long long pk2(float lo, float hi) {
    unsigned long long r;
    asm("mov.b64 %0, {%1,%2};" : "=l"(r) : "f"(lo), "f"(hi));
    return r;
}
__device__ __forceinline__ void ffma2(unsigned long long& d,
                                      unsigned long long a, unsigned long long b) {
    asm("fma.rn.f32x2 %0, %1, %2, %0;" : "+l"(d) : "l"(a), "l"(b));
}
__device__ __forceinline__ float2 upk2(unsigned long long v) {
    float2 r;
    asm("mov.b64 {%0,%1}, %2;" : "=f"(r.x), "=f"(r.y) : "l"(v));
    return r;
}

// ---------------------------------------------------------------------------
// Generic NT SGEMM:  C[m,n] = sum_k A[m,k] * B[n,k]  (+ bias / epilogues)
// Tile 64x64x16, 128 threads, 8x4 microtile with f32x2 accumulators.
// Scratch operands are bound per-MODE to the __device__ globals above,
// INSIDE the kernel (device context) — never via host-side symbol refs.
// ---------------------------------------------------------------------------
enum { MODE_BIAS_RELU = 0, MODE_BIAS = 1, MODE_GATES = 2, MODE_HS = 3, MODE_FINAL = 4 };

template<int MODE>
__global__ __launch_bounds__(128)
void sgemm_nt(const float* __restrict__ A,     // external A (BIAS_RELU: enc/gimg)
              const float* __restrict__ Bm,    // B matrix (N x K, row-major)
              const float* __restrict__ B2,    // second B (HS upper half)
              const float* __restrict__ bias,
              const float* __restrict__ bias2,
              float* __restrict__ Cout,        // external C (FINAL: d_out)
              int N, int K, int sel_or_t)
{
    __shared__ __align__(16) float As[16][64];
    __shared__ __align__(16) float Bs[16][64];

    const int tid = threadIdx.x;
    const int n0  = blockIdx.x * 64;
    const int m0C = blockIdx.y * 64;
    int m0A = m0C;

    int tt = 0, cnt = 0, bbase = 0;
    if (MODE == MODE_FINAL) {
        tt    = m0C >> 7;      // t index (tile never straddles t: 64 | 128)
        bbase = m0C & 127;
        cnt   = g_cnt[tt];
        if (bbase >= cnt) {    // whole tile inactive -> zero-fill, skip K loop
            for (int s = tid; s < 64 * 16; s += 128) {
                int r = s >> 4, c4 = (s & 15) << 2;
                int n = n0 + c4;
                int b = bbase + r;
                float* dst = &Cout[((size_t)(b * NSTEP + tt)) * N + n];
                if (n + 3 < N) {
                    *(float4*)dst = make_float4(0.f, 0.f, 0.f, 0.f);
                } else {
                    for (int q = 0; q < 4; q++)
                        if (n + q < N) dst[q] = 0.0f;
                }
            }
            return;
        }
    }
    if (MODE == MODE_HS) {
        if (m0C >= 128) { Bm = B2; bias = bias2; m0A = m0C - 128; }
    }
    if (MODE == MODE_GATES) {
        Bm   = g_Wpack;      // device-context binding (host shadow is a trap on ATS!)
        bias = g_bpack;
    }

    // ---- precompute per-thread A-row base pointers (K-invariant) ----
    const float* arow [2];   // primary source
    const float* arow2[2];   // GATES: g_H source for gk>=1024
    int rowi[2], kci[2];
    #pragma unroll
    for (int it = 0; it < 2; it++) {
        int s   = tid + it * 128;
        int row = s >> 2;
        rowi[it] = row;
        kci [it] = (s & 3) << 2;
        int gm  = m0A + row;
        if (MODE == MODE_BIAS_RELU) {
            int gr = (sel_or_t == 0) ? g_sortind[gm]
                                     : (g_sortind[gm / PP] * PP + gm % PP);
            arow[it] = A + (size_t)gr * ENCD;
        } else if (MODE == MODE_BIAS) {
            arow[it] = g_V + (size_t)gm * HD;
        } else if (MODE == MODE_GATES) {
            arow [it] = g_X + ((size_t)gm * NSTEP + sel_or_t) * 1024;
            arow2[it] = g_H + (size_t)gm * HD;
        } else if (MODE == MODE_HS) {
            arow[it] = ((m0C >= 128) ? g_S : g_HN) + (size_t)gm * HD;
        } else { // FINAL
            arow[it] = g_CH + (size_t)gm * HD;
        }
    }

    unsigned long long acc[4][4];
    #pragma unroll
    for (int i = 0; i < 4; i++)
        #pragma unroll
        for (int j = 0; j < 4; j++) acc[i][j] = 0ull;

    const int ty = tid >> 4;   // 0..7  -> rows ty*8 .. ty*8+7
    const int tx = tid & 15;   // 0..15 -> cols tx*4 .. tx*4+3

    for (int k0 = 0; k0 < K; k0 += 16) {
        // --- load A tile (64 rows x 16 k) as float4 ---
        #pragma unroll
        for (int it = 0; it < 2; it++) {
            int gk = k0 + kci[it];
            float4 v;
            if (MODE == MODE_GATES) {
                if (gk < 1024) v = *(const float4*)&arow [it][gk];
                else           v = *(const float4*)&arow2[it][gk - 1024];
            } else {
                v = *(const float4*)&arow[it][gk];
            }
            int row = rowi[it], kc = kci[it];
            As[kc + 0][row] = v.x; As[kc + 1][row] = v.y;
            As[kc + 2][row] = v.z; As[kc + 3][row] = v.w;
        }
        // --- load B tile (64 n-rows x 16 k), guard N tail ---
        #pragma unroll
        for (int it = 0; it < 2; it++) {
            int row = rowi[it], kc = kci[it];
            int gn  = n0 + row;
            float4 v = make_float4(0.f, 0.f, 0.f, 0.f);
            if (gn < N) v = *(const float4*)&Bm[(size_t)gn * K + k0 + kc];
            Bs[kc + 0][row] = v.x; Bs[kc + 1][row] = v.y;
            Bs[kc + 2][row] = v.z; Bs[kc + 3][row] = v.w;
        }
        __syncthreads();
        #pragma unroll
        for (int k = 0; k < 16; k++) {
            const ulonglong2* ap = (const ulonglong2*)&As[k][ty << 3];
            ulonglong2 aA = ap[0];   // rows (0,1),(2,3)
            ulonglong2 aB = ap[1];   // rows (4,5),(6,7)
            float4 bv = *(const float4*)&Bs[k][tx << 2];
            unsigned long long bd0 = pk2(bv.x, bv.x);
            unsigned long long bd1 = pk2(bv.y, bv.y);
            unsigned long long bd2 = pk2(bv.z, bv.z);
            unsigned long long bd3 = pk2(bv.w, bv.w);
            ffma2(acc[0][0], aA.x, bd0); ffma2(acc[0][1], aA.x, bd1);
            ffma2(acc[0][2], aA.x, bd2); ffma2(acc[0][3], aA.x, bd3);
            ffma2(acc[1][0], aA.y, bd0); ffma2(acc[1][1], aA.y, bd1);
            ffma2(acc[1][2], aA.y, bd2); ffma2(acc[1][3], aA.y, bd3);
            ffma2(acc[2][0], aB.x, bd0); ffma2(acc[2][1], aB.x, bd1);
            ffma2(acc[2][2], aB.x, bd2); ffma2(acc[2][3], aB.x, bd3);
            ffma2(acc[3][0], aB.y, bd0); ffma2(acc[3][1], aB.y, bd1);
            ffma2(acc[3][2], aB.y, bd2); ffma2(acc[3][3], aB.y, bd3);
        }
        __syncthreads();
    }

    // --- epilogue: pick destination per MODE (device-context binding) ---
    float* Cp;
    int ldc;
    if      (MODE == MODE_BIAS_RELU) { Cp = (sel_or_t == 0) ? g_vg : g_V; ldc = HD; }
    else if (MODE == MODE_BIAS)      { Cp = g_WV;   ldc = HD; }
    else if (MODE == MODE_GATES)     { Cp = g_G;    ldc = 2560; }
    else if (MODE == MODE_HS)        { Cp = g_WhWs; ldc = HD; }
    else                             { Cp = Cout;   ldc = N; }

    #pragma unroll
    for (int j = 0; j < 4; j++) {
        int n = n0 + (tx << 2) + j;
        if (n >= N) continue;
        float bn = bias[n];
        #pragma unroll
        for (int i2 = 0; i2 < 4; i2++) {
            float2 v = upk2(acc[i2][j]);
            int r0 = (ty << 3) + (i2 << 1);
            float v0 = v.x + bn, v1 = v.y + bn;
            if (MODE == MODE_BIAS_RELU) { v0 = fmaxf(v0, 0.f); v1 = fmaxf(v1, 0.f); }
            if (MODE == MODE_FINAL) {
                int b0 = bbase + r0;
                Cp[((size_t)(b0       * NSTEP + tt)) * N + n] = (b0     < cnt) ? v0 : 0.0f;
                Cp[((size_t)((b0 + 1) * NSTEP + tt)) * N + n] = (b0 + 1 < cnt) ? v1 : 0.0f;
            } else {
                Cp[(size_t)(m0C + r0    ) * ldc + n] = v0;
                Cp[(size_t)(m0C + r0 + 1) * ldc + n] = v1;
            }
        }
    }
}

// ---------------------------------------------------------------------------
// Prep: stable descending argsort of caplens, gather caps, cnt_t,
// and write the tail outputs (caps_s, dec_len, sort_ind as float).
// ---------------------------------------------------------------------------
__global__ void prep_kernel(const int* __restrict__ caplens,
                            const int* __restrict__ caps,
                            float* __restrict__ out, long long out_size)
{
    __shared__ int clsh[BB];
    int b = threadIdx.x;
    int cl = caplens[b];
    clsh[b] = cl;
    __syncthreads();
    int rank = 0;
    #pragma unroll 8
    for (int j = 0; j < BB; j++) {
        int cj = clsh[j];
        if (cj > cl || (cj == cl && j < b)) rank++;
    }
    g_sortind[rank] = b;
    g_declen[rank]  = cl - 1;
    __syncthreads();

    int si = g_sortind[b];
    for (int t = 0; t < TT; t++) g_capss[b * TT + t] = caps[si * TT + t];

    if (b < NSTEP) {
        int c = 0;
        for (int j = 0; j < BB; j++) if (g_declen[j] > b) c++;
        g_cnt[b] = c;
    }
    if (out_size >= PRED_ELEMS + 2816LL) {
        for (int t = 0; t < TT; t++)
            out[PRED_ELEMS + b * TT + t] = (float)g_capss[b * TT + t];
        out[PRED_ELEMS + 2560 + b] = (float)g_declen[b];
        out[PRED_ELEMS + 2688 + b] = (float)g_sortind[b];
    }
}

// ---------------------------------------------------------------------------
// Pack LSTM + gate weights into one (2560 x 1536) NT weight + fused bias
// ---------------------------------------------------------------------------
__global__ void pack_weights(const float* __restrict__ Wih, const float* __restrict__ Whh,
                             const float* __restrict__ Wx,  const float* __restrict__ Wph,
                             const float* __restrict__ bih, const float* __restrict__ bhh,
                             const float* __restrict__ bx,  const float* __restrict__ bph)
{
    int i = blockIdx.x * blockDim.x + threadIdx.x;   // 2560*1536 exactly
    int n = i / 1536;
    int k = i - n * 1536;
    float v;
    if (n < 2048) v = (k < 1024) ? Wih[n * 1024 + k] : Whh[n * 512 + (k - 1024)];
    else {
        int n2 = n - 2048;
        v = (k < 1024) ? Wx[n2 * 1024 + k] : Wph[n2 * 512 + (k - 1024)];
    }
    g_Wpack[i] = v;
    if (i < 2560)
        g_bpack[i] = (i < 2048) ? (bih[i] + bhh[i]) : (bx[i - 2048] + bph[i - 2048]);
}

// ---------------------------------------------------------------------------
// Build X = [emb(caps_s) | vg] for t = 0..18 ; layout (b, t, 1024)
// ---------------------------------------------------------------------------
__global__ void build_X(const float* __restrict__ embW)
{
    int i = blockIdx.x * blockDim.x + threadIdx.x;
    if (i >= BB * NSTEP * 1024) return;
    int k  = i & 1023;
    int bt = i >> 10;
    int t  = bt % NSTEP, b = bt / NSTEP;
    float v;
    if (k < 512) v = embW[(size_t)g_capss[b * TT + t] * 512 + k];
    else         v = g_vg[b * 512 + (k - 512)];
    g_X[i] = v;
}

__global__ void zero_hm()
{
    int i = blockIdx.x * blockDim.x + threadIdx.x;
    if (i < BB * HD) { g_H[i] = 0.f; g_M[i] = 0.f; }
}

// ---------------------------------------------------------------------------
// LSTM elementwise: gates -> m_new, h_new, s ; masked state update
// ---------------------------------------------------------------------------
__device__ __forceinline__ float sigm(float x) { return 1.0f / (1.0f + expf(-x)); }

__global__ void lstm_ew(int t)
{
    int idx = blockIdx.x * blockDim.x + threadIdx.x;   // 65536
    int b = idx >> 9, j = idx & 511;
    const float* G = g_G + (size_t)b * 2560;
    float ig = sigm(G[j]);
    float fg = sigm(G[512 + j]);
    float gg = tanhf(G[1024 + j]);
    float og = sigm(G[1536 + j]);
    float gt = sigm(G[2048 + j]);
    float mn = fg * g_M[idx] + ig * gg;
    float tm = tanhf(mn);
    float hn = og * tm;
    g_HN[idx] = hn;
    g_S[idx]  = gt * tm;
    if (t < g_declen[b]) { g_H[idx] = hn; g_M[idx] = mn; }
}

// ---------------------------------------------------------------------------
// Fused attention per (t): z, z_hat, softmaxes, context c, beta, CH output.
// One block per batch row b; 512 threads (16 warps).
// ---------------------------------------------------------------------------
__global__ __launch_bounds__(512)
void attn_fused(int t,
                const float* __restrict__ wa,    const float* __restrict__ ba,
                const float* __restrict__ wahat, const float* __restrict__ bahat)
{
    __shared__ float shWh[512];
    __shared__ float zsh[64];
    __shared__ float alph[64];
    __shared__ float betash;
    int b = blockIdx.x;
    int tid = threadIdx.x;
    shWh[tid] = g_WhWs[b * 512 + tid];
    __syncthreads();

    int warp = tid >> 5, lane = tid & 31;
    for (int idx = warp; idx < 50; idx += 16) {
        float sum = 0.f;
        if (idx < 49) {
            const float* wv = g_WV + ((size_t)(b * PP + idx)) * 512;
            #pragma unroll
            for (int e = lane; e < 512; e += 32)
                sum += tanhf(wv[e] + shWh[e]) * wa[e];
        } else {
            const float* ws = g_WhWs + (size_t)(128 + b) * 512;
            #pragma unroll
            for (int e = lane; e < 512; e += 32)
                sum += tanhf(ws[e] + shWh[e]) * wahat[e];
        }
        #pragma unroll
        for (int o = 16; o; o >>= 1) sum += __shfl_down_sync(0xffffffffu, sum, o);
        if (lane == 0) zsh[idx] = sum + (idx < 49 ? ba[0] : bahat[0]);
    }
    __syncthreads();

    if (warp == 0) {
        float z0 = (lane < 49)      ? zsh[lane]      : -1e30f;
        float z1 = (lane + 32 < 49) ? zsh[lane + 32] : -1e30f;
        float mx = fmaxf(z0, z1);
        #pragma unroll
        for (int o = 16; o; o >>= 1) mx = fmaxf(mx, __shfl_xor_sync(0xffffffffu, mx, o));
        float e0 = (lane < 49)      ? expf(z0 - mx) : 0.f;
        float e1 = (lane + 32 < 49) ? expf(z1 - mx) : 0.f;
        float sm = e0 + e1;
        #pragma unroll
        for (int o = 16; o; o >>= 1) sm += __shfl_xor_sync(0xffffffffu, sm, o);
        float inv = 1.f / sm;
        if (lane < 49)      alph[lane]      = e0 * inv;
        if (lane + 32 < 49) alph[lane + 32] = e1 * inv;
        if (lane == 0) {
            float zh = zsh[49];
            float m2 = fmaxf(mx, zh);
            float s2 = sm * expf(mx - m2) + expf(zh - m2);
            betash = expf(zh - m2) / s2;
        }
    }
    __syncthreads();

    float beta = betash;
    float c = 0.f;
    const float* Vb = g_V + (size_t)b * PP * 512 + tid;
    #pragma unroll 7
    for (int p = 0; p < PP; p++) c += alph[p] * Vb[p * 512];
    int idx = b * 512 + tid;
    float ch = beta * g_S[idx] + (1.f - beta) * c + g_HN[idx];
    g_CH[((size_t)t * BB + b) * 512 + tid] = ch;
}

// ---------------------------------------------------------------------------
// Host launcher — kernel launches ONLY (graph-capture safe, no runtime APIs,
// no host-side references to __device__ symbols)
// ---------------------------------------------------------------------------
extern "C" void kernel_launch(void* const* d_in, const int* in_sizes, int n_in,
                              void* d_out, int out_size)
{
    (void)in_sizes; (void)n_in;
    const float* enc    = (const float*)d_in[0];
    const float* gimg   = (const float*)d_in[1];
    const int*   caps   = (const int*)  d_in[2];
    const int*   caplens= (const int*)  d_in[3];
    const float* embW   = (const float*)d_in[4];
    const float* Wih    = (const float*)d_in[5];
    const float* Whh    = (const float*)d_in[6];
    const float* bih    = (const float*)d_in[7];
    const float* bhh    = (const float*)d_in[8];
    const float* Wg     = (const float*)d_in[9];
    const float* bg     = (const float*)d_in[10];
    const float* Wi     = (const float*)d_in[11];
    const float* bi     = (const float*)d_in[12];
    const float* Wx     = (const float*)d_in[13];
    const float* bx     = (const float*)d_in[14];
    const float* Wph    = (const float*)d_in[15];
    const float* bph    = (const float*)d_in[16];
    const float* attWh  = (const float*)d_in[17];
    const float* attbh  = (const float*)d_in[18];
    const float* attWs  = (const float*)d_in[19];
    const float* attbs  = (const float*)d_in[20];
    const float* attWV  = (const float*)d_in[21];
    const float* attbV  = (const float*)d_in[22];
    const float* wa     = (const float*)d_in[23];
    const float* ba     = (const float*)d_in[24];
    const float* wahat  = (const float*)d_in[25];
    const float* bahat  = (const float*)d_in[26];
    const float* finalW = (const float*)d_in[27];
    const float* finalb = (const float*)d_in[28];
    float* out = (float*)d_out;

    // --- setup phase ---
    prep_kernel<<<1, 128>>>(caplens, caps, out, (long long)out_size);
    pack_weights<<<(2560 * 1536) / 256, 256>>>(Wih, Whh, Wx, Wph, bih, bhh, bx, bph);
    zero_hm<<<256, 256>>>();

    // vg = relu(gimg_sorted @ Wg^T + bg)   (sel=0)
    sgemm_nt<MODE_BIAS_RELU><<<dim3(8, 2), 128>>>(gimg, Wg, nullptr,
        bg, nullptr, nullptr, HD, ENCD, 0);
    // V = relu(enc_sorted @ Wi^T + bi)     (sel=1)
    sgemm_nt<MODE_BIAS_RELU><<<dim3(8, MROWS / 64), 128>>>(enc, Wi, nullptr,
        bi, nullptr, nullptr, HD, ENCD, 1);
    // X = [emb | vg]
    build_X<<<(BB * NSTEP * 1024 + 255) / 256, 256>>>(embW);
    // WV = V @ att_WV^T + bV
    sgemm_nt<MODE_BIAS><<<dim3(8, MROWS / 64), 128>>>(nullptr, attWV, nullptr,
        attbV, nullptr, nullptr, HD, HD, 0);

    // --- 19 sequential decode steps ---
    for (int t = 0; t < NSTEP; t++) {
        // gates(2048) + gate-pre(512): [x_t | h] @ Wpack^T + bpack
        // (Wpack/bpack bound inside the kernel in device context)
        sgemm_nt<MODE_GATES><<<dim3(40, 2), 128>>>(nullptr, nullptr, nullptr,
            nullptr, nullptr, nullptr, 2560, 1536, t);
        lstm_ew<<<BB * HD / 256, 256>>>(t);
        // [Wh ; Ws] = [h_new @ att_Wh^T + bh ; s @ att_Ws^T + bs]
        sgemm_nt<MODE_HS><<<dim3(8, 4), 128>>>(nullptr, attWh, attWs,
            attbh, attbs, nullptr, HD, HD, 0);
        attn_fused<<<BB, 512>>>(t, wa, ba, wahat, bahat);
    }

    // --- batched final projection: preds[b,t,:] = (c_hat + h_new) @ final_W^T + final_b
    sgemm_nt<MODE_FINAL><<<dim3((VOC + 63) / 64, NSTEP * BB / 64), 128>>>(nullptr,
        finalW, nullptr, finalb, nullptr, out, VOC, HD, 0);
}

// round 10
// speedup vs baseline: 1.0340x; 1.0340x over previous
#include <cuda_runtime.h>
#include <cuda_bf16.h>

// ---------------------------------------------------------------------------
// Problem constants
// ---------------------------------------------------------------------------
#define BB    128
#define PP    49
#define TT    20
#define NSTEP 19
#define HD    512
#define ENCD  2048
#define VOC   20000
#define MROWS (BB*PP)                      // 6272
#define MACT_PAD (38*64)                   // 2432 = BB*NSTEP, padded rowmap
#define PRED_ELEMS (128LL*19LL*20000LL)

// ---------------------------------------------------------------------------
// Scratch (static device memory; referenced ONLY from device code)
// ---------------------------------------------------------------------------
__device__ __align__(128) float g_V   [MROWS*HD];
__device__ __align__(128) float g_WV  [MROWS*HD];
__device__ __align__(128) float g_Wpack[2560*1536];    // [W_ih|W_hh ; Wx|Wph]
__device__ __align__(128) float g_bpack[2560];
__device__ __align__(128) float g_GX  [BB*NSTEP*2560]; // x-part of gates, all t
__device__ __align__(128) float g_CH  [NSTEP*BB*HD];
__device__ __align__(128) float g_G   [BB*2560];
__device__ __align__(128) float g_H   [BB*HD];
__device__ __align__(128) float g_M   [BB*HD];
__device__ __align__(128) float g_HN  [BB*HD];
__device__ __align__(128) float g_S   [BB*HD];
__device__ __align__(128) float g_WhWs[2*BB*HD];
__device__ __align__(128) float g_vg  [BB*HD];
__device__ int g_sortind[BB];
__device__ int g_declen [BB];
__device__ int g_cnt    [NSTEP];
__device__ int g_capss  [BB*TT];
__device__ int g_rowmap [MACT_PAD];   // compact active (t*128+b), padded
__device__ int g_nact;

// ---------------------------------------------------------------------------
// f32x2 helpers (FFMA2 — 2x fp32 FMA rate, PTX-only)
// ---------------------------------------------------------------------------
__device__ __forceinline__ void ffma2(unsigned long long& d,
                                      unsigned long long a, unsigned long long b) {
    asm("fma.rn.f32x2 %0, %1, %2, %0;" : "+l"(d) : "l"(a), "l"(b));
}
__device__ __forceinline__ float2 upk2(unsigned long long v) {
    float2 r;
    asm("mov.b64 {%0,%1}, %2;" : "=f"(r.x), "=f"(r.y) : "l"(v));
    return r;
}

// ---------------------------------------------------------------------------
// NT SGEMM, double-buffered, B duplicated in smem for direct f32x2 operands.
// Tile BM x 64 x 16, 2*BM threads, 8x4 microtile per thread.
// ---------------------------------------------------------------------------
enum { MODE_BIAS_RELU = 0, MODE_BIAS = 1, MODE_GSTEP = 2, MODE_HS = 3,
       MODE_FINAL = 4, MODE_GXB = 5 };

template<int MODE, int BM>
__global__ __launch_bounds__(2*BM)
void sgemm_nt(const float* __restrict__ A,     // external A (enc/gimg/embW)
              const float* __restrict__ Bm,    // B (N x ldb row-major)
              const float* __restrict__ B2,    // HS second B
              const float* __restrict__ bias,
              const float* __restrict__ bias2,
              float* __restrict__ Cout,        // FINAL: d_out
              int N, int K, int t)
{
    constexpr int THREADS = 2 * BM;
    constexpr int ASTR = BM + 4;
    constexpr int BSTR = 132;
    constexpr int NB_IT = (BM == 64) ? 2 : 1;
    __shared__ __align__(16) float As [2][16][ASTR];
    __shared__ __align__(16) float Bsd[2][16][BSTR];

    const int tid = threadIdx.x;
    const int n0  = blockIdx.x * 64;
    const int m0C = blockIdx.y * BM;
    int m0A = m0C;

    if (MODE == MODE_GSTEP) { if (m0C >= g_cnt[t]) return; }
    if (MODE == MODE_FINAL) { if (m0C >= g_nact)   return; }
    if (MODE == MODE_HS) {
        if (m0C >= 128) { Bm = B2; bias = bias2; m0A = m0C - 128; }
        if (m0A >= g_cnt[t]) return;
    }
    if (MODE == MODE_GSTEP) Bm = g_Wpack + 1024;   // device-context binding
    if (MODE == MODE_GXB)   { Bm = g_Wpack; bias = g_bpack; }

    const int ldb = (MODE == MODE_GSTEP || MODE == MODE_GXB) ? 1536 : K;

    // ---- per-thread K-invariant A-row pointers (2 slots) ----
    const float* arow [2];
    const float* arow2[2];   // GXB: vg source for gk>=512
    int rowi[2], kci[2];
    #pragma unroll
    for (int it = 0; it < 2; it++) {
        int s   = tid + it * THREADS;
        int row = s >> 2;
        rowi[it] = row;
        kci [it] = (s & 3) << 2;
        int gm  = m0A + row;
        if (MODE == MODE_BIAS_RELU) {
            int gr = (t == 0) ? g_sortind[gm]
                              : (g_sortind[gm / PP] * PP + gm % PP);
            arow[it] = A + (size_t)gr * ENCD;
        } else if (MODE == MODE_BIAS) {
            arow[it] = g_V + (size_t)gm * HD;
        } else if (MODE == MODE_GSTEP) {
            arow[it] = g_H + (size_t)gm * HD;
        } else if (MODE == MODE_HS) {
            arow[it] = ((m0C >= 128) ? g_S : g_HN) + (size_t)gm * HD;
        } else if (MODE == MODE_FINAL) {
            arow[it] = g_CH + (size_t)g_rowmap[gm] * HD;   // padded-safe
        } else { // GXB: row gm -> (b = gm/19, tt = gm%19)
            int b  = gm / NSTEP;
            int ts = gm - b * NSTEP;
            arow [it] = A + (size_t)g_capss[b * TT + ts] * HD;  // emb (k<512)
            arow2[it] = g_vg + (size_t)b * HD;                  // vg  (k>=512)
        }
    }
    // ---- per-thread B-row info ----
    const float* brow[NB_IT];
    int bn[NB_IT], bkci[NB_IT];
    bool bok[NB_IT];
    #pragma unroll
    for (int it = 0; it < NB_IT; it++) {
        int s  = tid + it * THREADS;
        int nr = s >> 2;
        bn  [it] = nr;
        bkci[it] = (s & 3) << 2;
        int gn = n0 + nr;
        bok [it] = (gn < N);
        brow[it] = Bm + (size_t)(bok[it] ? gn : 0) * ldb;
    }

    float4 aR[2], bR[NB_IT];

    #define LOAD_TILE(k0)                                                     \
        {                                                                     \
            _Pragma("unroll")                                                 \
            for (int it = 0; it < 2; it++) {                                  \
                int gk = (k0) + kci[it];                                      \
                if (MODE == MODE_GXB) {                                       \
                    aR[it] = (gk < HD) ? *(const float4*)&arow[it][gk]        \
                                       : *(const float4*)&arow2[it][gk - HD]; \
                } else {                                                      \
                    aR[it] = *(const float4*)&arow[it][gk];                   \
                }                                                             \
            }                                                                 \
            _Pragma("unroll")                                                 \
            for (int it = 0; it < NB_IT; it++) {                              \
                bR[it] = bok[it] ? *(const float4*)&brow[it][(k0) + bkci[it]] \
                                 : make_float4(0.f, 0.f, 0.f, 0.f);           \
            }                                                                 \
        }

    #define STORE_TILE(buf)                                                   \
        {                                                                     \
            _Pragma("unroll")                                                 \
            for (int it = 0; it < 2; it++) {                                  \
                int kc = kci[it], row = rowi[it];                             \
                As[buf][kc + 0][row] = aR[it].x;                              \
                As[buf][kc + 1][row] = aR[it].y;                              \
                As[buf][kc + 2][row] = aR[it].z;                              \
                As[buf][kc + 3][row] = aR[it].w;                              \
            }                                                                 \
            _Pragma("unroll")                                                 \
            for (int it = 0; it < NB_IT; it++) {                              \
                int kc = bkci[it], nr2 = bn[it] * 2;                          \
                *(float2*)&Bsd[buf][kc + 0][nr2] = make_float2(bR[it].x, bR[it].x); \
                *(float2*)&Bsd[buf][kc + 1][nr2] = make_float2(bR[it].y, bR[it].y); \
                *(float2*)&Bsd[buf][kc + 2][nr2] = make_float2(bR[it].z, bR[it].z); \
                *(float2*)&Bsd[buf][kc + 3][nr2] = make_float2(bR[it].w, bR[it].w); \
            }                                                                 \
        }

    unsigned long long acc[4][4];
    #pragma unroll
    for (int i = 0; i < 4; i++)
        #pragma unroll
        for (int j = 0; j < 4; j++) acc[i][j] = 0ull;

    const int ty = tid >> 4;
    const int tx = tid & 15;

    LOAD_TILE(0);
    STORE_TILE(0);
    __syncthreads();
    int buf = 0;
    const int KT = K >> 4;
    for (int kt = 0; kt < KT; kt++) {
        if (kt + 1 < KT) LOAD_TILE((kt + 1) << 4);
        #pragma unroll
        for (int k = 0; k < 16; k++) {
            const ulonglong2* ap = (const ulonglong2*)&As[buf][k][ty << 3];
            ulonglong2 aA = ap[0];
            ulonglong2 aB = ap[1];
            const ulonglong2* bp = (const ulonglong2*)&Bsd[buf][k][tx << 3];
            ulonglong2 b01 = bp[0];
            ulonglong2 b23 = bp[1];
            ffma2(acc[0][0], aA.x, b01.x); ffma2(acc[0][1], aA.x, b01.y);
            ffma2(acc[0][2], aA.x, b23.x); ffma2(acc[0][3], aA.x, b23.y);
            ffma2(acc[1][0], aA.y, b01.x); ffma2(acc[1][1], aA.y, b01.y);
            ffma2(acc[1][2], aA.y, b23.x); ffma2(acc[1][3], aA.y, b23.y);
            ffma2(acc[2][0], aB.x, b01.x); ffma2(acc[2][1], aB.x, b01.y);
            ffma2(acc[2][2], aB.x, b23.x); ffma2(acc[2][3], aB.x, b23.y);
            ffma2(acc[3][0], aB.y, b01.x); ffma2(acc[3][1], aB.y, b01.y);
            ffma2(acc[3][2], aB.y, b23.x); ffma2(acc[3][3], aB.y, b23.y);
        }
        if (kt + 1 < KT) {
            STORE_TILE(buf ^ 1);
            __syncthreads();
            buf ^= 1;
        }
    }
    #undef LOAD_TILE
    #undef STORE_TILE

    // ---- epilogue ----
    float* Cp;
    int ldc;
    if      (MODE == MODE_BIAS_RELU) { Cp = (t == 0) ? g_vg : g_V; ldc = HD; }
    else if (MODE == MODE_BIAS)      { Cp = g_WV;   ldc = HD; }
    else if (MODE == MODE_GSTEP)     { Cp = g_G;    ldc = 2560; }
    else if (MODE == MODE_HS)        { Cp = g_WhWs; ldc = HD; }
    else if (MODE == MODE_GXB)       { Cp = g_GX;   ldc = 2560; }
    else                             { Cp = Cout;   ldc = N; }

    const int nact = (MODE == MODE_FINAL) ? g_nact : 0;
    #pragma unroll
    for (int j = 0; j < 4; j++) {
        int n = n0 + (tx << 2) + j;
        if (n >= N) continue;
        float bn2 = (MODE == MODE_GSTEP) ? 0.0f : bias[n];
        #pragma unroll
        for (int i2 = 0; i2 < 4; i2++) {
            float2 v = upk2(acc[i2][j]);
            int r0 = (ty << 3) + (i2 << 1);
            float v0 = v.x + bn2, v1 = v.y + bn2;
            if (MODE == MODE_BIAS_RELU) { v0 = fmaxf(v0, 0.f); v1 = fmaxf(v1, 0.f); }
            if (MODE == MODE_GSTEP) {
                int b0 = m0C + r0;
                v0 += g_GX[((size_t)b0       * NSTEP + t) * 2560 + n];
                v1 += g_GX[((size_t)(b0 + 1) * NSTEP + t) * 2560 + n];
                Cp[(size_t)b0 * 2560 + n]       = v0;
                Cp[(size_t)(b0 + 1) * 2560 + n] = v1;
            } else if (MODE == MODE_FINAL) {
                int i0 = m0C + r0;
                if (i0 < nact) {
                    int rm = g_rowmap[i0];                 // t*128+b
                    int b  = rm & 127, ts = rm >> 7;
                    Cp[((size_t)(b * NSTEP + ts)) * N + n] = v0;
                }
                if (i0 + 1 < nact) {
                    int rm = g_rowmap[i0 + 1];
                    int b  = rm & 127, ts = rm >> 7;
                    Cp[((size_t)(b * NSTEP + ts)) * N + n] = v1;
                }
            } else {
                Cp[(size_t)(m0C + r0)     * ldc + n] = v0;
                Cp[(size_t)(m0C + r0 + 1) * ldc + n] = v1;
            }
        }
    }
}

// ---------------------------------------------------------------------------
// Prep: stable descending argsort, caps gather, cnt_t, compact rowmap, tails
// ---------------------------------------------------------------------------
__global__ void prep_kernel(const int* __restrict__ caplens,
                            const int* __restrict__ caps,
                            float* __restrict__ out, long long out_size)
{
    __shared__ int clsh[BB];
    __shared__ int off[NSTEP + 1];
    int b = threadIdx.x;
    int cl = caplens[b];
    clsh[b] = cl;
    __syncthreads();
    int rank = 0;
    #pragma unroll 8
    for (int j = 0; j < BB; j++) {
        int cj = clsh[j];
        if (cj > cl || (cj == cl && j < b)) rank++;
    }
    g_sortind[rank] = b;
    g_declen[rank]  = cl - 1;
    __syncthreads();

    int si = g_sortind[b];
    for (int t = 0; t < TT; t++) g_capss[b * TT + t] = caps[si * TT + t];

    if (b < NSTEP) {
        int c = 0;
        for (int j = 0; j < BB; j++) if (g_declen[j] > b) c++;
        g_cnt[b] = c;
    }
    __syncthreads();
    if (b == 0) {
        int o = 0;
        for (int t = 0; t < NSTEP; t++) { off[t] = o; o += g_cnt[t]; }
        off[NSTEP] = o;
        g_nact = o;
    }
    __syncthreads();
    for (int t = 0; t < NSTEP; t++)
        if (b < g_cnt[t]) g_rowmap[off[t] + b] = t * BB + b;
    __syncthreads();
    int nact = off[NSTEP];
    int lastrm = g_rowmap[nact - 1];
    for (int i = nact + b; i < MACT_PAD; i += BB) g_rowmap[i] = lastrm;

    // zero initial h, m
    for (int i = b; i < BB * HD; i += BB) { g_H[i] = 0.f; g_M[i] = 0.f; }

    if (out_size >= PRED_ELEMS + 2816LL) {
        for (int t = 0; t < TT; t++)
            out[PRED_ELEMS + b * TT + t] = (float)g_capss[b * TT + t];
        out[PRED_ELEMS + 2560 + b] = (float)g_declen[b];
        out[PRED_ELEMS + 2688 + b] = (float)g_sortind[b];
    }
}

// ---------------------------------------------------------------------------
// Pack LSTM + gate weights into one (2560 x 1536) NT weight + fused bias
// ---------------------------------------------------------------------------
__global__ void pack_weights(const float* __restrict__ Wih, const float* __restrict__ Whh,
                             const float* __restrict__ Wx,  const float* __restrict__ Wph,
                             const float* __restrict__ bih, const float* __restrict__ bhh,
                             const float* __restrict__ bx,  const float* __restrict__ bph)
{
    int i = blockIdx.x * blockDim.x + threadIdx.x;
    int n = i / 1536;
    int k = i - n * 1536;
    float v;
    if (n < 2048) v = (k < 1024) ? Wih[n * 1024 + k] : Whh[n * 512 + (k - 1024)];
    else {
        int n2 = n - 2048;
        v = (k < 1024) ? Wx[n2 * 1024 + k] : Wph[n2 * 512 + (k - 1024)];
    }
    g_Wpack[i] = v;
    if (i < 2560)
        g_bpack[i] = (i < 2048) ? (bih[i] + bhh[i]) : (bx[i - 2048] + bph[i - 2048]);
}

// ---------------------------------------------------------------------------
// Zero-fill predictions of inactive (b,t) rows
// ---------------------------------------------------------------------------
__global__ void zero_inactive(float* __restrict__ out)
{
    int bt = blockIdx.x;            // 0..2431
    int b = bt / NSTEP, t = bt - b * NSTEP;
    if (t < g_declen[b]) return;    // active -> written by FINAL GEMM
    float4* dst = (float4*)(out + (size_t)bt * VOC);
    for (int i = threadIdx.x; i < VOC / 4; i += blockDim.x)
        dst[i] = make_float4(0.f, 0.f, 0.f, 0.f);
}

// ---------------------------------------------------------------------------
// LSTM elementwise (active rows only)
// ---------------------------------------------------------------------------
__device__ __forceinline__ float sigm(float x) { return 1.0f / (1.0f + expf(-x)); }

__global__ void lstm_ew(int t)
{
    if ((int)(blockIdx.x >> 1) >= g_cnt[t]) return;
    int idx = blockIdx.x * 256 + threadIdx.x;
    int b = idx >> 9, j = idx & 511;
    const float* G = g_G + (size_t)b * 2560;
    float ig = sigm(G[j]);
    float fg = sigm(G[512 + j]);
    float gg = tanhf(G[1024 + j]);
    float og = sigm(G[1536 + j]);
    float gt = sigm(G[2048 + j]);
    float mn = fg * g_M[idx] + ig * gg;
    float tm = tanhf(mn);
    float hn = og * tm;
    g_HN[idx] = hn;
    g_S[idx]  = gt * tm;
    if (t < g_declen[b]) { g_H[idx] = hn; g_M[idx] = mn; }
}

// ---------------------------------------------------------------------------
// Fused attention per t (active rows only)
// ---------------------------------------------------------------------------
__global__ __launch_bounds__(512)
void attn_fused(int t,
                const float* __restrict__ wa,    const float* __restrict__ ba,
                const float* __restrict__ wahat, const float* __restrict__ bahat)
{
    int b = blockIdx.x;
    if (b >= g_cnt[t]) return;
    __shared__ float shWh[512];
    __shared__ float zsh[64];
    __shared__ float alph[64];
    __shared__ float betash;
    int tid = threadIdx.x;
    shWh[tid] = g_WhWs[b * 512 + tid];
    __syncthreads();

    int warp = tid >> 5, lane = tid & 31;
    for (int idx = warp; idx < 50; idx += 16) {
        float sum = 0.f;
        if (idx < 49) {
            const float* wv = g_WV + ((size_t)(b * PP + idx)) * 512;
            #pragma unroll
            for (int e = lane; e < 512; e += 32)
                sum += tanhf(wv[e] + shWh[e]) * wa[e];
        } else {
            const float* ws = g_WhWs + (size_t)(128 + b) * 512;
            #pragma unroll
            for (int e = lane; e < 512; e += 32)
                sum += tanhf(ws[e] + shWh[e]) * wahat[e];
        }
        #pragma unroll
        for (int o = 16; o; o >>= 1) sum += __shfl_down_sync(0xffffffffu, sum, o);
        if (lane == 0) zsh[idx] = sum + (idx < 49 ? ba[0] : bahat[0]);
    }
    __syncthreads();

    if (warp == 0) {
        float z0 = (lane < 49)      ? zsh[lane]      : -1e30f;
        float z1 = (lane + 32 < 49) ? zsh[lane + 32] : -1e30f;
        float mx = fmaxf(z0, z1);
        #pragma unroll
        for (int o = 16; o; o >>= 1) mx = fmaxf(mx, __shfl_xor_sync(0xffffffffu, mx, o));
        float e0 = (lane < 49)      ? expf(z0 - mx) : 0.f;
        float e1 = (lane + 32 < 49) ? expf(z1 - mx) : 0.f;
        float sm = e0 + e1;
        #pragma unroll
        for (int o = 16; o; o >>= 1) sm += __shfl_xor_sync(0xffffffffu, sm, o);
        float inv = 1.f / sm;
        if (lane < 49)      alph[lane]      = e0 * inv;
        if (lane + 32 < 49) alph[lane + 32] = e1 * inv;
        if (lane == 0) {
            float zh = zsh[49];
            float m2 = fmaxf(mx, zh);
            float s2 = sm * expf(mx - m2) + expf(zh - m2);
            betash = expf(zh - m2) / s2;
        }
    }
    __syncthreads();

    float beta = betash;
    float c = 0.f;
    const float* Vb = g_V + (size_t)b * PP * 512 + tid;
    #pragma unroll 7
    for (int p = 0; p < PP; p++) c += alph[p] * Vb[p * 512];
    int idx = b * 512 + tid;
    float ch = beta * g_S[idx] + (1.f - beta) * c + g_HN[idx];
    g_CH[((size_t)t * BB + b) * 512 + tid] = ch;
}

// ---------------------------------------------------------------------------
// Host launcher — kernel launches only
// ---------------------------------------------------------------------------
extern "C" void kernel_launch(void* const* d_in, const int* in_sizes, int n_in,
                              void* d_out, int out_size)
{
    (void)in_sizes; (void)n_in;
    const float* enc    = (const float*)d_in[0];
    const float* gimg   = (const float*)d_in[1];
    const int*   caps   = (const int*)  d_in[2];
    const int*   caplens= (const int*)  d_in[3];
    const float* embW   = (const float*)d_in[4];
    const float* Wih    = (const float*)d_in[5];
    const float* Whh    = (const float*)d_in[6];
    const float* bih    = (const float*)d_in[7];
    const float* bhh    = (const float*)d_in[8];
    const float* Wg     = (const float*)d_in[9];
    const float* bg     = (const float*)d_in[10];
    const float* Wi     = (const float*)d_in[11];
    const float* bi     = (const float*)d_in[12];
    const float* bx     = (const float*)d_in[14];
    const float* Wx     = (const float*)d_in[13];
    const float* Wph    = (const float*)d_in[15];
    const float* bph    = (const float*)d_in[16];
    const float* attWh  = (const float*)d_in[17];
    const float* attbh  = (const float*)d_in[18];
    const float* attWs  = (const float*)d_in[19];
    const float* attbs  = (const float*)d_in[20];
    const float* attWV  = (const float*)d_in[21];
    const float* attbV  = (const float*)d_in[22];
    const float* wa     = (const float*)d_in[23];
    const float* ba     = (const float*)d_in[24];
    const float* wahat  = (const float*)d_in[25];
    const float* bahat  = (const float*)d_in[26];
    const float* finalW = (const float*)d_in[27];
    const float* finalb = (const float*)d_in[28];
    float* out = (float*)d_out;

    // --- setup ---
    prep_kernel<<<1, 128>>>(caplens, caps, out, (long long)out_size);
    pack_weights<<<(2560 * 1536) / 256, 256>>>(Wih, Whh, Wx, Wph, bih, bhh, bx, bph);
    zero_inactive<<<BB * NSTEP, 256>>>(out);

    // vg = relu(gimg_s @ Wg^T + bg)        [sel=0, BM=64]
    sgemm_nt<MODE_BIAS_RELU, 64><<<dim3(8, 2), 128>>>(gimg, Wg, nullptr,
        bg, nullptr, nullptr, HD, ENCD, 0);
    // V = relu(enc_s @ Wi^T + bi)          [sel=1, BM=128]
    sgemm_nt<MODE_BIAS_RELU, 128><<<dim3(8, MROWS / 128), 256>>>(enc, Wi, nullptr,
        bi, nullptr, nullptr, HD, ENCD, 1);
    // GX = [emb_t | vg] @ Wpack[:, :1024]^T + bpack   (all t at once, BM=128)
    sgemm_nt<MODE_GXB, 128><<<dim3(40, BB * NSTEP / 128), 256>>>(embW, nullptr, nullptr,
        nullptr, nullptr, nullptr, 2560, 1024, 0);
    // WV = V @ att_WV^T + bV               [BM=128]
    sgemm_nt<MODE_BIAS, 128><<<dim3(8, MROWS / 128), 256>>>(nullptr, attWV, nullptr,
        attbV, nullptr, nullptr, HD, HD, 0);

    // --- 19 sequential decode steps ---
    for (int t = 0; t < NSTEP; t++) {
        // G = GX[:,t] + h @ Wpack[:,1024:]^T   (K=512, BM=64)
        sgemm_nt<MODE_GSTEP, 64><<<dim3(40, 2), 128>>>(nullptr, nullptr, nullptr,
            nullptr, nullptr, nullptr, 2560, HD, t);
        lstm_ew<<<BB * HD / 256, 256>>>(t);
        // [Wh ; Ws]
        sgemm_nt<MODE_HS, 64><<<dim3(8, 4), 128>>>(nullptr, attWh, attWs,
            attbh, attbs, nullptr, HD, HD, t);
        attn_fused<<<BB, 512>>>(t, wa, ba, wahat, bahat);
    }

    // --- batched final projection over compacted active rows ---
    sgemm_nt<MODE_FINAL, 64><<<dim3((VOC + 63) / 64, MACT_PAD / 64), 128>>>(nullptr,
        finalW, nullptr, finalb, nullptr, out, VOC, HD, 0);
}

// round 12
// speedup vs baseline: 1.2619x; 1.2203x over previous
#include <cuda_runtime.h>
#include <cuda_bf16.h>

// ---------------------------------------------------------------------------
// Problem constants
// ---------------------------------------------------------------------------
#define BB    128
#define PP    49
#define TT    20
#define NSTEP 19
#define HD    512
#define ENCD  2048
#define VOC   20000
#define MROWS (BB*PP)                      // 6272
#define MACT_PAD (38*64)                   // 2432 = BB*NSTEP
#define PRED_ELEMS (128LL*19LL*20000LL)
#define KS_G  4                            // split-K for gates step GEMM
#define KS_HS 4                            // split-K for Wh/Ws GEMM
#define KS_VG 8                            // split-K for vg GEMM

// ---------------------------------------------------------------------------
// Scratch (static device memory; referenced ONLY from device code)
// ---------------------------------------------------------------------------
__device__ __align__(128) float g_V   [MROWS*HD];
__device__ __align__(128) float g_WV  [MROWS*HD];
__device__ __align__(128) float g_Wpack[2560*1536];    // [W_ih|W_hh ; Wx|Wph]
__device__ __align__(128) float g_bpack[2560];
__device__ __align__(128) float g_GX  [BB*NSTEP*2560]; // x-part of gates, all t
__device__ __align__(128) float g_CH  [NSTEP*BB*HD];
__device__ __align__(128) float g_Gp  [KS_G*BB*2560];  // split-K partials (gates)
__device__ __align__(128) float g_H   [BB*HD];
__device__ __align__(128) float g_M   [BB*HD];
__device__ __align__(128) float g_HN  [BB*HD];
__device__ __align__(128) float g_S   [BB*HD];
__device__ __align__(128) float g_WhWsP[KS_HS*2*BB*HD]; // split-K partials (Wh|Ws)
__device__ __align__(128) float g_vg  [BB*HD];
__device__ __align__(128) float g_vgP [KS_VG*BB*HD];
__device__ int g_sortind[BB];
__device__ int g_declen [BB];
__device__ int g_cnt    [NSTEP];
__device__ int g_capss  [BB*TT];
__device__ int g_rowmap [MACT_PAD];
__device__ int g_nact;

// ---------------------------------------------------------------------------
// f32x2 helpers (FFMA2 — 2x fp32 FMA rate, PTX-only)
// ---------------------------------------------------------------------------
__device__ __forceinline__ void ffma2(unsigned long long& d,
                                      unsigned long long a, unsigned long long b) {
    asm("fma.rn.f32x2 %0, %1, %2, %0;" : "+l"(d) : "l"(a), "l"(b));
}
__device__ __forceinline__ float2 upk2(unsigned long long v) {
    float2 r;
    asm("mov.b64 {%0,%1}, %2;" : "=f"(r.x), "=f"(r.y) : "l"(v));
    return r;
}

// ---------------------------------------------------------------------------
// NT SGEMM: double-buffered smem, B duplicated for direct f32x2 operands,
// manually software-pipelined fragment loads (hide LDS latency under FFMA2).
// Tile BM x 64 x 16, 2*BM threads, 8x4 microtile, optional split-K (grid.z).
// ---------------------------------------------------------------------------
enum { MODE_BIAS_RELU = 0, MODE_BIAS = 1, MODE_GSTEP = 2, MODE_HS = 3,
       MODE_FINAL = 4, MODE_GXB = 5 };

template<int MODE, int BM, int KSPLIT>
__global__ __launch_bounds__(2*BM)
void sgemm_nt(const float* __restrict__ A,     // external A (enc/gimg/embW)
              const float* __restrict__ Bm,    // B (N x ldb row-major)
              const float* __restrict__ B2,    // HS second B
              const float* __restrict__ bias,
              float* __restrict__ Cout,        // FINAL: d_out
              int N, int K, int t)             // K = per-split K
{
    constexpr int THREADS = 2 * BM;
    constexpr int ASTR = BM + 4;
    constexpr int BSTR = 132;
    constexpr int NB_IT = (BM == 64) ? 2 : 1;
    __shared__ __align__(16) float As [2][16][ASTR];
    __shared__ __align__(16) float Bsd[2][16][BSTR];

    const int tid = threadIdx.x;
    const int n0  = blockIdx.x * 64;
    const int m0C = blockIdx.y * BM;
    const int kz  = (KSPLIT > 1) ? blockIdx.z : 0;
    int m0A = m0C;

    if (MODE == MODE_GSTEP) { if (m0C >= g_cnt[t]) return; }
    if (MODE == MODE_FINAL) { if (m0C >= g_nact)   return; }
    if (MODE == MODE_HS) {
        if (m0C >= 128) { Bm = B2; m0A = m0C - 128; }
        if (m0A >= g_cnt[t]) return;
    }
    if (MODE == MODE_GSTEP) Bm = g_Wpack + 1024;   // device-context binding
    if (MODE == MODE_GXB)   { Bm = g_Wpack; bias = g_bpack; }

    const int ldb = (MODE == MODE_GSTEP || MODE == MODE_GXB) ? 1536
                  : (MODE == MODE_BIAS_RELU ? ENCD : HD);

    // ---- per-thread K-invariant A-row pointers (2 slots) ----
    const float* arow [2];
    const float* arow2[2];   // GXB: vg source for gk>=512
    int rowi[2], kci[2];
    #pragma unroll
    for (int it = 0; it < 2; it++) {
        int s   = tid + it * THREADS;
        int row = s >> 2;
        rowi[it] = row;
        kci [it] = (s & 3) << 2;
        int gm  = m0A + row;
        if (MODE == MODE_BIAS_RELU) {
            int gr = (t == 0) ? g_sortind[gm]
                              : (g_sortind[gm / PP] * PP + gm % PP);
            arow[it] = A + (size_t)gr * ENCD + kz * K;
        } else if (MODE == MODE_BIAS) {
            arow[it] = g_V + (size_t)gm * HD;
        } else if (MODE == MODE_GSTEP) {
            arow[it] = g_H + (size_t)gm * HD + kz * K;
        } else if (MODE == MODE_HS) {
            arow[it] = ((m0C >= 128) ? g_S : g_HN) + (size_t)gm * HD + kz * K;
        } else if (MODE == MODE_FINAL) {
            arow[it] = g_CH + (size_t)g_rowmap[gm] * HD;
        } else { // GXB
            int b  = gm / NSTEP;
            int ts = gm - b * NSTEP;
            arow [it] = A + (size_t)g_capss[b * TT + ts] * HD;
            arow2[it] = g_vg + (size_t)b * HD;
        }
    }
    // ---- per-thread B-row info ----
    const float* brow[NB_IT];
    int bn[NB_IT], bkci[NB_IT];
    bool bok[NB_IT];
    #pragma unroll
    for (int it = 0; it < NB_IT; it++) {
        int s  = tid + it * THREADS;
        int nr = s >> 2;
        bn  [it] = nr;
        bkci[it] = (s & 3) << 2;
        int gn = n0 + nr;
        bok [it] = (gn < N);
        brow[it] = Bm + (size_t)(bok[it] ? gn : 0) * ldb + kz * K;
    }

    float4 aR[2], bR[NB_IT];

    #define LOAD_TILE(k0)                                                     \
        {                                                                     \
            _Pragma("unroll")                                                 \
            for (int it = 0; it < 2; it++) {                                  \
                int gk = (k0) + kci[it];                                      \
                if (MODE == MODE_GXB) {                                       \
                    aR[it] = (gk < HD) ? *(const float4*)&arow[it][gk]        \
                                       : *(const float4*)&arow2[it][gk - HD]; \
                } else {                                                      \
                    aR[it] = *(const float4*)&arow[it][gk];                   \
                }                                                             \
            }                                                                 \
            _Pragma("unroll")                                                 \
            for (int it = 0; it < NB_IT; it++) {                              \
                bR[it] = bok[it] ? *(const float4*)&brow[it][(k0) + bkci[it]] \
                                 : make_float4(0.f, 0.f, 0.f, 0.f);           \
            }                                                                 \
        }

    #define STORE_TILE(buf)                                                   \
        {                                                                     \
            _Pragma("unroll")                                                 \
            for (int it = 0; it < 2; it++) {                                  \
                int kc = kci[it], row = rowi[it];                             \
                As[buf][kc + 0][row] = aR[it].x;                              \
                As[buf][kc + 1][row] = aR[it].y;                              \
                As[buf][kc + 2][row] = aR[it].z;                              \
                As[buf][kc + 3][row] = aR[it].w;                              \
            }                                                                 \
            _Pragma("unroll")                                                 \
            for (int it = 0; it < NB_IT; it++) {                              \
                int kc = bkci[it], nr2 = bn[it] * 2;                          \
                *(float2*)&Bsd[buf][kc + 0][nr2] = make_float2(bR[it].x, bR[it].x); \
                *(float2*)&Bsd[buf][kc + 1][nr2] = make_float2(bR[it].y, bR[it].y); \
                *(float2*)&Bsd[buf][kc + 2][nr2] = make_float2(bR[it].z, bR[it].z); \
                *(float2*)&Bsd[buf][kc + 3][nr2] = make_float2(bR[it].w, bR[it].w); \
            }                                                                 \
        }

    #define LDFRAG(buf, k, aA, aB, b01, b23)                                  \
        {                                                                     \
            const ulonglong2* ap = (const ulonglong2*)&As[buf][k][ty << 3];   \
            aA = ap[0]; aB = ap[1];                                           \
            const ulonglong2* bp = (const ulonglong2*)&Bsd[buf][k][tx << 3];  \
            b01 = bp[0]; b23 = bp[1];                                         \
        }

    unsigned long long acc[4][4];
    #pragma unroll
    for (int i = 0; i < 4; i++)
        #pragma unroll
        for (int j = 0; j < 4; j++) acc[i][j] = 0ull;

    const int ty = tid >> 4;
    const int tx = tid & 15;

    LOAD_TILE(0);
    STORE_TILE(0);
    __syncthreads();
    int buf = 0;
    const int KT = K >> 4;
    for (int kt = 0; kt < KT; kt++) {
        if (kt + 1 < KT) LOAD_TILE((kt + 1) << 4);
        ulonglong2 aAc, aBc, b01c, b23c, aAn, aBn, b01n, b23n;
        LDFRAG(buf, 0, aAc, aBc, b01c, b23c);
        #pragma unroll
        for (int k = 0; k < 16; k++) {
            if (k < 15) LDFRAG(buf, k + 1, aAn, aBn, b01n, b23n);
            ffma2(acc[0][0], aAc.x, b01c.x); ffma2(acc[0][1], aAc.x, b01c.y);
            ffma2(acc[0][2], aAc.x, b23c.x); ffma2(acc[0][3], aAc.x, b23c.y);
            ffma2(acc[1][0], aAc.y, b01c.x); ffma2(acc[1][1], aAc.y, b01c.y);
            ffma2(acc[1][2], aAc.y, b23c.x); ffma2(acc[1][3], aAc.y, b23c.y);
            ffma2(acc[2][0], aBc.x, b01c.x); ffma2(acc[2][1], aBc.x, b01c.y);
            ffma2(acc[2][2], aBc.x, b23c.x); ffma2(acc[2][3], aBc.x, b23c.y);
            ffma2(acc[3][0], aBc.y, b01c.x); ffma2(acc[3][1], aBc.y, b01c.y);
            ffma2(acc[3][2], aBc.y, b23c.x); ffma2(acc[3][3], aBc.y, b23c.y);
            if (k < 15) { aAc = aAn; aBc = aBn; b01c = b01n; b23c = b23n; }
        }
        if (kt + 1 < KT) {
            STORE_TILE(buf ^ 1);
            __syncthreads();
            buf ^= 1;
        }
    }
    #undef LOAD_TILE
    #undef STORE_TILE
    #undef LDFRAG

    // ---- epilogue ----
    float* Cp;
    int ldc;
    if (KSPLIT > 1) {
        if      (MODE == MODE_GSTEP)     { Cp = g_Gp    + (size_t)kz * (BB * 2560); ldc = 2560; }
        else if (MODE == MODE_HS)        { Cp = g_WhWsP + (size_t)kz * (2 * BB * HD); ldc = HD; }
        else /* BIAS_RELU vg */          { Cp = g_vgP   + (size_t)kz * (BB * HD);   ldc = HD; }
    } else {
        if      (MODE == MODE_BIAS_RELU) { Cp = g_V;    ldc = HD; }
        else if (MODE == MODE_BIAS)      { Cp = g_WV;   ldc = HD; }
        else if (MODE == MODE_GXB)       { Cp = g_GX;   ldc = 2560; }
        else                             { Cp = Cout;   ldc = N; }
    }

    const int nact = (MODE == MODE_FINAL) ? g_nact : 0;
    #pragma unroll
    for (int j = 0; j < 4; j++) {
        int n = n0 + (tx << 2) + j;
        if (n >= N) continue;
        float bn2 = (KSPLIT > 1) ? 0.0f : bias[n];
        #pragma unroll
        for (int i2 = 0; i2 < 4; i2++) {
            float2 v = upk2(acc[i2][j]);
            int r0 = (ty << 3) + (i2 << 1);
            float v0 = v.x + bn2, v1 = v.y + bn2;
            if (MODE == MODE_BIAS_RELU && KSPLIT == 1) {
                v0 = fmaxf(v0, 0.f); v1 = fmaxf(v1, 0.f);
            }
            if (MODE == MODE_FINAL) {
                int i0 = m0C + r0;
                if (i0 < nact) {
                    int rm = g_rowmap[i0];
                    int b  = rm & 127, ts = rm >> 7;
                    Cp[((size_t)(b * NSTEP + ts)) * N + n] = v0;
                }
                if (i0 + 1 < nact) {
                    int rm = g_rowmap[i0 + 1];
                    int b  = rm & 127, ts = rm >> 7;
                    Cp[((size_t)(b * NSTEP + ts)) * N + n] = v1;
                }
            } else {
                Cp[(size_t)(m0C + r0)     * ldc + n] = v0;
                Cp[(size_t)(m0C + r0 + 1) * ldc + n] = v1;
            }
        }
    }
}

// ---------------------------------------------------------------------------
// Prep: stable descending argsort, caps gather, cnt_t, compact rowmap, tails
// ---------------------------------------------------------------------------
__global__ void prep_kernel(const int* __restrict__ caplens,
                            const int* __restrict__ caps,
                            float* __restrict__ out, long long out_size)
{
    __shared__ int clsh[BB];
    __shared__ int off[NSTEP + 1];
    int b = threadIdx.x;
    int cl = caplens[b];
    clsh[b] = cl;
    __syncthreads();
    int rank = 0;
    #pragma unroll 8
    for (int j = 0; j < BB; j++) {
        int cj = clsh[j];
        if (cj > cl || (cj == cl && j < b)) rank++;
    }
    g_sortind[rank] = b;
    g_declen[rank]  = cl - 1;
    __syncthreads();

    int si = g_sortind[b];
    for (int t = 0; t < TT; t++) g_capss[b * TT + t] = caps[si * TT + t];

    if (b < NSTEP) {
        int c = 0;
        for (int j = 0; j < BB; j++) if (g_declen[j] > b) c++;
        g_cnt[b] = c;
    }
    __syncthreads();
    if (b == 0) {
        int o = 0;
        for (int t = 0; t < NSTEP; t++) { off[t] = o; o += g_cnt[t]; }
        off[NSTEP] = o;
        g_nact = o;
    }
    __syncthreads();
    for (int t = 0; t < NSTEP; t++)
        if (b < g_cnt[t]) g_rowmap[off[t] + b] = t * BB + b;
    __syncthreads();
    int nact = off[NSTEP];
    int lastrm = g_rowmap[nact - 1];
    for (int i = nact + b; i < MACT_PAD; i += BB) g_rowmap[i] = lastrm;

    for (int i = b; i < BB * HD; i += BB) { g_H[i] = 0.f; g_M[i] = 0.f; }

    if (out_size >= PRED_ELEMS + 2816LL) {
        for (int t = 0; t < TT; t++)
            out[PRED_ELEMS + b * TT + t] = (float)g_capss[b * TT + t];
        out[PRED_ELEMS + 2560 + b] = (float)g_declen[b];
        out[PRED_ELEMS + 2688 + b] = (float)g_sortind[b];
    }
}

// ---------------------------------------------------------------------------
// Pack LSTM + gate weights into one (2560 x 1536) NT weight + fused bias
// ---------------------------------------------------------------------------
__global__ void pack_weights(const float* __restrict__ Wih, const float* __restrict__ Whh,
                             const float* __restrict__ Wx,  const float* __restrict__ Wph,
                             const float* __restrict__ bih, const float* __restrict__ bhh,
                             const float* __restrict__ bx,  const float* __restrict__ bph)
{
    int i = blockIdx.x * blockDim.x + threadIdx.x;
    int n = i / 1536;
    int k = i - n * 1536;
    float v;
    if (n < 2048) v = (k < 1024) ? Wih[n * 1024 + k] : Whh[n * 512 + (k - 1024)];
    else {
        int n2 = n - 2048;
        v = (k < 1024) ? Wx[n2 * 1024 + k] : Wph[n2 * 512 + (k - 1024)];
    }
    g_Wpack[i] = v;
    if (i < 2560)
        g_bpack[i] = (i < 2048) ? (bih[i] + bhh[i]) : (bx[i - 2048] + bph[i - 2048]);
}

// ---------------------------------------------------------------------------
// vg split-K reduction + bias + relu
// ---------------------------------------------------------------------------
__global__ void vg_reduce(const float* __restrict__ bg)
{
    int i = blockIdx.x * 256 + threadIdx.x;     // 65536
    float v = bg[i & 511];
    #pragma unroll
    for (int z = 0; z < KS_VG; z++) v += g_vgP[z * (BB * HD) + i];
    g_vg[i] = fmaxf(v, 0.f);
}

// ---------------------------------------------------------------------------
// Zero-fill predictions of inactive (b,t) rows
// ---------------------------------------------------------------------------
__global__ void zero_inactive(float* __restrict__ out)
{
    int bt = blockIdx.x;            // 0..2431
    int b = bt / NSTEP, t = bt - b * NSTEP;
    if (t < g_declen[b]) return;
    float4* dst = (float4*)(out + (size_t)bt * VOC);
    for (int i = threadIdx.x; i < VOC / 4; i += blockDim.x)
        dst[i] = make_float4(0.f, 0.f, 0.f, 0.f);
}

// ---------------------------------------------------------------------------
// LSTM elementwise (active rows only): sums split-K partials + GX
// ---------------------------------------------------------------------------
__device__ __forceinline__ float sigm(float x) { return 1.0f / (1.0f + expf(-x)); }

__global__ void lstm_ew(int t)
{
    if ((int)(blockIdx.x >> 1) >= g_cnt[t]) return;
    int idx = blockIdx.x * 256 + threadIdx.x;
    int b = idx >> 9, j = idx & 511;
    const float* GX = g_GX + ((size_t)b * NSTEP + t) * 2560;
    float ga[5];
    #pragma unroll
    for (int g5 = 0; g5 < 5; g5++) {
        int n = g5 * 512 + j;
        float v = GX[n];
        #pragma unroll
        for (int z = 0; z < KS_G; z++)
            v += g_Gp[(size_t)z * (BB * 2560) + (size_t)b * 2560 + n];
        ga[g5] = v;
    }
    float ig = sigm(ga[0]);
    float fg = sigm(ga[1]);
    float gg = tanhf(ga[2]);
    float og = sigm(ga[3]);
    float gt = sigm(ga[4]);
    float mn = fg * g_M[idx] + ig * gg;
    float tm = tanhf(mn);
    float hn = og * tm;
    g_HN[idx] = hn;
    g_S[idx]  = gt * tm;
    if (t < g_declen[b]) { g_H[idx] = hn; g_M[idx] = mn; }
}

// ---------------------------------------------------------------------------
// Fused attention per t (active rows only): sums HS split-K partials + biases
// ---------------------------------------------------------------------------
__global__ __launch_bounds__(512)
void attn_fused(int t,
                const float* __restrict__ attbh, const float* __restrict__ attbs,
                const float* __restrict__ wa,    const float* __restrict__ ba,
                const float* __restrict__ wahat, const float* __restrict__ bahat)
{
    int b = blockIdx.x;
    if (b >= g_cnt[t]) return;
    __shared__ float shWh[512];
    __shared__ float shWs[512];
    __shared__ float zsh[64];
    __shared__ float alph[64];
    __shared__ float betash;
    int tid = threadIdx.x;
    {
        float vh = attbh[tid], vs = attbs[tid];
        #pragma unroll
        for (int z = 0; z < KS_HS; z++) {
            vh += g_WhWsP[(size_t)z * (2 * BB * HD) + (size_t)b * HD + tid];
            vs += g_WhWsP[(size_t)z * (2 * BB * HD) + (size_t)(BB + b) * HD + tid];
        }
        shWh[tid] = vh;
        shWs[tid] = vs;
    }
    __syncthreads();

    int warp = tid >> 5, lane = tid & 31;
    for (int idx = warp; idx < 50; idx += 16) {
        float sum = 0.f;
        if (idx < 49) {
            const float* wv = g_WV + ((size_t)(b * PP + idx)) * 512;
            #pragma unroll
            for (int e = lane; e < 512; e += 32)
                sum += tanhf(wv[e] + shWh[e]) * wa[e];
        } else {
            #pragma unroll
            for (int e = lane; e < 512; e += 32)
                sum += tanhf(shWs[e] + shWh[e]) * wahat[e];
        }
        #pragma unroll
        for (int o = 16; o; o >>= 1) sum += __shfl_down_sync(0xffffffffu, sum, o);
        if (lane == 0) zsh[idx] = sum + (idx < 49 ? ba[0] : bahat[0]);
    }
    __syncthreads();

    if (warp == 0) {
        float z0 = (lane < 49)      ? zsh[lane]      : -1e30f;
        float z1 = (lane + 32 < 49) ? zsh[lane + 32] : -1e30f;
        float mx = fmaxf(z0, z1);
        #pragma unroll
        for (int o = 16; o; o >>= 1) mx = fmaxf(mx, __shfl_xor_sync(0xffffffffu, mx, o));
        float e0 = (lane < 49)      ? expf(z0 - mx) : 0.f;
        float e1 = (lane + 32 < 49) ? expf(z1 - mx) : 0.f;
        float sm = e0 + e1;
        #pragma unroll
        for (int o = 16; o; o >>= 1) sm += __shfl_xor_sync(0xffffffffu, sm, o);
        float inv = 1.f / sm;
        if (lane < 49)      alph[lane]      = e0 * inv;
        if (lane + 32 < 49) alph[lane + 32] = e1 * inv;
        if (lane == 0) {
            float zh = zsh[49];
            float m2 = fmaxf(mx, zh);
            float s2 = sm * expf(mx - m2) + expf(zh - m2);
            betash = expf(zh - m2) / s2;
        }
    }
    __syncthreads();

    float beta = betash;
    float c = 0.f;
    const float* Vb = g_V + (size_t)b * PP * 512 + tid;
    #pragma unroll 7
    for (int p = 0; p < PP; p++) c += alph[p] * Vb[p * 512];
    int idx = b * 512 + tid;
    float ch = beta * g_S[idx] + (1.f - beta) * c + g_HN[idx];
    g_CH[((size_t)t * BB + b) * 512 + tid] = ch;
}

// ---------------------------------------------------------------------------
// Host launcher — kernel launches only
// ---------------------------------------------------------------------------
extern "C" void kernel_launch(void* const* d_in, const int* in_sizes, int n_in,
                              void* d_out, int out_size)
{
    (void)in_sizes; (void)n_in;
    const float* enc    = (const float*)d_in[0];
    const float* gimg   = (const float*)d_in[1];
    const int*   caps   = (const int*)  d_in[2];
    const int*   caplens= (const int*)  d_in[3];
    const float* embW   = (const float*)d_in[4];
    const float* Wih    = (const float*)d_in[5];
    const float* Whh    = (const float*)d_in[6];
    const float* bih    = (const float*)d_in[7];
    const float* bhh    = (const float*)d_in[8];
    const float* Wg     = (const float*)d_in[9];
    const float* bg     = (const float*)d_in[10];
    const float* Wi     = (const float*)d_in[11];
    const float* bi     = (const float*)d_in[12];
    const float* Wx     = (const float*)d_in[13];
    const float* bx     = (const float*)d_in[14];
    const float* Wph    = (const float*)d_in[15];
    const float* bph    = (const float*)d_in[16];
    const float* attWh  = (const float*)d_in[17];
    const float* attbh  = (const float*)d_in[18];
    const float* attWs  = (const float*)d_in[19];
    const float* attbs  = (const float*)d_in[20];
    const float* attWV  = (const float*)d_in[21];
    const float* attbV  = (const float*)d_in[22];
    const float* wa     = (const float*)d_in[23];
    const float* ba     = (const float*)d_in[24];
    const float* wahat  = (const float*)d_in[25];
    const float* bahat  = (const float*)d_in[26];
    const float* finalW = (const float*)d_in[27];
    const float* finalb = (const float*)d_in[28];
    float* out = (float*)d_out;

    // --- setup ---
    prep_kernel<<<1, 128>>>(caplens, caps, out, (long long)out_size);
    pack_weights<<<(2560 * 1536) / 256, 256>>>(Wih, Whh, Wx, Wph, bih, bhh, bx, bph);
    zero_inactive<<<BB * NSTEP, 256>>>(out);

    // vg partials: gimg_s @ Wg^T   (split-K 8, K=256 each)
    sgemm_nt<MODE_BIAS_RELU, 64, KS_VG><<<dim3(8, 2, KS_VG), 128>>>(gimg, Wg, nullptr,
        nullptr, nullptr, HD, ENCD / KS_VG, 0);
    vg_reduce<<<BB * HD / 256, 256>>>(bg);
    // V = relu(enc_s @ Wi^T + bi)
    sgemm_nt<MODE_BIAS_RELU, 128, 1><<<dim3(8, MROWS / 128), 256>>>(enc, Wi, nullptr,
        bi, nullptr, HD, ENCD, 1);
    // GX = [emb_t | vg] @ Wpack[:, :1024]^T + bpack   (all t)
    sgemm_nt<MODE_GXB, 128, 1><<<dim3(40, BB * NSTEP / 128), 256>>>(embW, nullptr, nullptr,
        nullptr, nullptr, 2560, 1024, 0);
    // WV = V @ att_WV^T + bV
    sgemm_nt<MODE_BIAS, 128, 1><<<dim3(8, MROWS / 128), 256>>>(nullptr, attWV, nullptr,
        attbV, nullptr, HD, HD, 0);

    // --- 19 sequential decode steps ---
    for (int t = 0; t < NSTEP; t++) {
        // gate partials: h @ Wpack[:,1024:]^T   (split-K 4, K=128 each)
        sgemm_nt<MODE_GSTEP, 64, KS_G><<<dim3(40, 2, KS_G), 128>>>(nullptr, nullptr, nullptr,
            nullptr, nullptr, 2560, HD / KS_G, t);
        lstm_ew<<<BB * HD / 256, 256>>>(t);
        // [Wh ; Ws] partials (split-K 4)
        sgemm_nt<MODE_HS, 64, KS_HS><<<dim3(8, 4, KS_HS), 128>>>(nullptr, attWh, attWs,
            nullptr, nullptr, HD, HD / KS_HS, t);
        attn_fused<<<BB, 512>>>(t, attbh, attbs, wa, ba, wahat, bahat);
    }

    // --- batched final projection over compacted active rows ---
    sgemm_nt<MODE_FINAL, 64, 1><<<dim3((VOC + 63) / 64, MACT_PAD / 64), 128>>>(nullptr,
        finalW, nullptr, finalb, out, VOC, HD, 0);
}

// round 13
// speedup vs baseline: 1.9034x; 1.5084x over previous
#include <cuda_runtime.h>
#include <cuda_bf16.h>

// ---------------------------------------------------------------------------
// Problem constants
// ---------------------------------------------------------------------------
#define BB    128
#define PP    49
#define TT    20
#define NSTEP 19
#define HD    512
#define ENCD  2048
#define VOC   20000
#define MROWS (BB*PP)                      // 6272
#define MACT_PAD (38*64)                   // 2432 = BB*NSTEP
#define PRED_ELEMS (128LL*19LL*20000LL)
#define KS_G  4
#define KS_HS 4
#define KS_VG 8

// ---------------------------------------------------------------------------
// Scratch (static device memory; referenced ONLY from device code)
// ---------------------------------------------------------------------------
__device__ __align__(128) float g_V   [MROWS*HD];
__device__ __align__(128) float g_WV  [MROWS*HD];
__device__ __align__(128) float g_Wpack[2560*1536];    // [W_ih|W_hh ; Wx|Wph]
__device__ __align__(128) float g_bpack[2560];
__device__ __align__(128) float g_GX  [BB*NSTEP*2560]; // x-part of gates, all t
__device__ __align__(128) float g_CH  [NSTEP*BB*HD];
__device__ __align__(128) float g_Gp  [KS_G*BB*2560];
__device__ __align__(128) float g_H   [BB*HD];
__device__ __align__(128) float g_M   [BB*HD];
__device__ __align__(128) float g_HN  [BB*HD];
__device__ __align__(128) float g_S   [BB*HD];
__device__ __align__(128) float g_WhWsP[KS_HS*2*BB*HD];
__device__ __align__(128) float g_vg  [BB*HD];
__device__ __align__(128) float g_vgP [KS_VG*BB*HD];
__device__ int g_sortind[BB];
__device__ int g_declen [BB];
__device__ int g_cnt    [NSTEP];
__device__ int g_capss  [BB*TT];
__device__ int g_rowmap [MACT_PAD];
__device__ int g_nact;

// ---------------------------------------------------------------------------
// f32x2 helpers
// ---------------------------------------------------------------------------
__device__ __forceinline__ void ffma2(unsigned long long& d,
                                      unsigned long long a, unsigned long long b) {
    asm("fma.rn.f32x2 %0, %1, %2, %0;" : "+l"(d) : "l"(a), "l"(b));
}
__device__ __forceinline__ float2 upk2(unsigned long long v) {
    float2 r;
    asm("mov.b64 {%0,%1}, %2;" : "=f"(r.x), "=f"(r.y) : "l"(v));
    return r;
}

// ===========================================================================
// BIG GEMM: 128x64 tile, 128 threads, 8x8 microtile, double-buffered,
// conflict-free duplicated-B layout (8 groups x 20-float slots).
// ===========================================================================
enum { B_V = 0, B_WV = 1, B_GXB = 2, B_FINAL = 3 };

template<int MODE>
__global__ __launch_bounds__(128)
void sgemm_big(const float* __restrict__ A,     // enc / embW
               const float* __restrict__ Bm,    // weights (N x ldb)
               const float* __restrict__ bias,
               float* __restrict__ Cout,        // FINAL: d_out
               int N, int K)
{
    __shared__ __align__(16) float As [2][16][132];
    __shared__ __align__(16) float Bsd[2][16][164];   // 8 groups x 20 + pad

    const int tid = threadIdx.x;
    const int n0  = blockIdx.x * 64;
    const int m0  = blockIdx.y * 128;

    int nact = 0;
    if (MODE == B_FINAL) { nact = g_nact; if (m0 >= nact) return; }
    if (MODE == B_GXB)   { Bm = g_Wpack; bias = g_bpack; }
    const int ldb = (MODE == B_GXB) ? 1536 : ((MODE == B_V) ? ENCD : HD);

    // ---- per-thread A-row pointers (4 slots, K-invariant) ----
    const float* arow [4];
    const float* arow2[4];
    int rowi[4], kci[4];
    #pragma unroll
    for (int it = 0; it < 4; it++) {
        int s   = tid + it * 128;
        int row = s >> 2;
        rowi[it] = row;
        kci [it] = (s & 3) << 2;
        int gm = m0 + row;
        if (MODE == B_V) {
            int gr = g_sortind[gm / PP] * PP + gm % PP;
            arow[it] = A + (size_t)gr * ENCD;
        } else if (MODE == B_WV) {
            arow[it] = g_V + (size_t)gm * HD;
        } else if (MODE == B_FINAL) {
            arow[it] = g_CH + (size_t)g_rowmap[gm] * HD;
        } else { // GXB
            int b  = gm / NSTEP;
            int ts = gm - b * NSTEP;
            arow [it] = A + (size_t)g_capss[b * TT + ts] * HD;
            arow2[it] = g_vg + (size_t)b * HD;
        }
    }
    // ---- per-thread B info (2 slots) ----
    const float* brow[2];
    int bc[2], bkci[2];
    bool bok[2];
    #pragma unroll
    for (int it = 0; it < 2; it++) {
        int s  = tid + it * 128;
        int c  = s >> 2;
        bc  [it] = c;
        bkci[it] = (s & 3) << 2;
        int gn = n0 + c;
        bok [it] = (gn < N);
        brow[it] = Bm + (size_t)(bok[it] ? gn : 0) * ldb;
    }

    float4 aR[4], bR[2];

    #define BLOAD_TILE(k0)                                                    \
        {                                                                     \
            _Pragma("unroll")                                                 \
            for (int it = 0; it < 4; it++) {                                  \
                int gk = (k0) + kci[it];                                      \
                if (MODE == B_GXB) {                                          \
                    aR[it] = (gk < HD) ? *(const float4*)&arow[it][gk]        \
                                       : *(const float4*)&arow2[it][gk - HD]; \
                } else {                                                      \
                    aR[it] = *(const float4*)&arow[it][gk];                   \
                }                                                             \
            }                                                                 \
            _Pragma("unroll")                                                 \
            for (int it = 0; it < 2; it++) {                                  \
                bR[it] = bok[it] ? *(const float4*)&brow[it][(k0) + bkci[it]] \
                                 : make_float4(0.f, 0.f, 0.f, 0.f);           \
            }                                                                 \
        }

    #define BSTORE_TILE(buf)                                                  \
        {                                                                     \
            _Pragma("unroll")                                                 \
            for (int it = 0; it < 4; it++) {                                  \
                int kc = kci[it], row = rowi[it];                             \
                As[buf][kc + 0][row] = aR[it].x;                              \
                As[buf][kc + 1][row] = aR[it].y;                              \
                As[buf][kc + 2][row] = aR[it].z;                              \
                As[buf][kc + 3][row] = aR[it].w;                              \
            }                                                                 \
            _Pragma("unroll")                                                 \
            for (int it = 0; it < 2; it++) {                                  \
                int kc = bkci[it];                                            \
                int go = (bc[it] >> 3) * 20 + (bc[it] & 7) * 2;               \
                *(float2*)&Bsd[buf][kc + 0][go] = make_float2(bR[it].x, bR[it].x); \
                *(float2*)&Bsd[buf][kc + 1][go] = make_float2(bR[it].y, bR[it].y); \
                *(float2*)&Bsd[buf][kc + 2][go] = make_float2(bR[it].z, bR[it].z); \
                *(float2*)&Bsd[buf][kc + 3][go] = make_float2(bR[it].w, bR[it].w); \
            }                                                                 \
        }

    #define BLDFRAG(buf, k, aA, aB, b0, b1, b2, b3)                           \
        {                                                                     \
            const ulonglong2* ap = (const ulonglong2*)&As[buf][k][ty << 3];   \
            aA = ap[0]; aB = ap[1];                                           \
            const float* bbase = &Bsd[buf][k][tx * 20];                       \
            b0 = *(const ulonglong2*)(bbase + 0);                             \
            b1 = *(const ulonglong2*)(bbase + 4);                             \
            b2 = *(const ulonglong2*)(bbase + 8);                             \
            b3 = *(const ulonglong2*)(bbase + 12);                            \
        }

    unsigned long long acc[4][8];
    #pragma unroll
    for (int i = 0; i < 4; i++)
        #pragma unroll
        for (int j = 0; j < 8; j++) acc[i][j] = 0ull;

    const int ty = tid >> 3;   // 0..15 -> rows ty*8..+7
    const int tx = tid & 7;    // 0..7  -> cols tx*8..+7

    BLOAD_TILE(0);
    BSTORE_TILE(0);
    __syncthreads();
    int buf = 0;
    const int KT = K >> 4;
    for (int kt = 0; kt < KT; kt++) {
        if (kt + 1 < KT) BLOAD_TILE((kt + 1) << 4);
        ulonglong2 aAc, aBc, aAn, aBn;
        ulonglong2 b0c, b1c, b2c, b3c, b0n, b1n, b2n, b3n;
        BLDFRAG(buf, 0, aAc, aBc, b0c, b1c, b2c, b3c);
        #pragma unroll
        for (int k = 0; k < 16; k++) {
            if (k < 15) BLDFRAG(buf, k + 1, aAn, aBn, b0n, b1n, b2n, b3n);
            ffma2(acc[0][0], aAc.x, b0c.x); ffma2(acc[0][1], aAc.x, b0c.y);
            ffma2(acc[0][2], aAc.x, b1c.x); ffma2(acc[0][3], aAc.x, b1c.y);
            ffma2(acc[0][4], aAc.x, b2c.x); ffma2(acc[0][5], aAc.x, b2c.y);
            ffma2(acc[0][6], aAc.x, b3c.x); ffma2(acc[0][7], aAc.x, b3c.y);
            ffma2(acc[1][0], aAc.y, b0c.x); ffma2(acc[1][1], aAc.y, b0c.y);
            ffma2(acc[1][2], aAc.y, b1c.x); ffma2(acc[1][3], aAc.y, b1c.y);
            ffma2(acc[1][4], aAc.y, b2c.x); ffma2(acc[1][5], aAc.y, b2c.y);
            ffma2(acc[1][6], aAc.y, b3c.x); ffma2(acc[1][7], aAc.y, b3c.y);
            ffma2(acc[2][0], aBc.x, b0c.x); ffma2(acc[2][1], aBc.x, b0c.y);
            ffma2(acc[2][2], aBc.x, b1c.x); ffma2(acc[2][3], aBc.x, b1c.y);
            ffma2(acc[2][4], aBc.x, b2c.x); ffma2(acc[2][5], aBc.x, b2c.y);
            ffma2(acc[2][6], aBc.x, b3c.x); ffma2(acc[2][7], aBc.x, b3c.y);
            ffma2(acc[3][0], aBc.y, b0c.x); ffma2(acc[3][1], aBc.y, b0c.y);
            ffma2(acc[3][2], aBc.y, b1c.x); ffma2(acc[3][3], aBc.y, b1c.y);
            ffma2(acc[3][4], aBc.y, b2c.x); ffma2(acc[3][5], aBc.y, b2c.y);
            ffma2(acc[3][6], aBc.y, b3c.x); ffma2(acc[3][7], aBc.y, b3c.y);
            if (k < 15) {
                aAc = aAn; aBc = aBn;
                b0c = b0n; b1c = b1n; b2c = b2n; b3c = b3n;
            }
        }
        if (kt + 1 < KT) {
            BSTORE_TILE(buf ^ 1);
            __syncthreads();
            buf ^= 1;
        }
    }
    #undef BLOAD_TILE
    #undef BSTORE_TILE
    #undef BLDFRAG

    // ---- epilogue: vectorized stores ----
    float* Cp;
    int ldc;
    if      (MODE == B_V)   { Cp = g_V;  ldc = HD; }
    else if (MODE == B_WV)  { Cp = g_WV; ldc = HD; }
    else if (MODE == B_GXB) { Cp = g_GX; ldc = 2560; }
    else                    { Cp = Cout; ldc = N; }

    const int nb = n0 + (tx << 3);
    float bs[8];
    #pragma unroll
    for (int j = 0; j < 8; j++)
        bs[j] = (nb + j < N) ? bias[nb + j] : 0.f;

    #pragma unroll
    for (int i = 0; i < 4; i++) {
        #pragma unroll
        for (int half = 0; half < 2; half++) {
            int r  = (ty << 3) + (i << 1) + half;
            int i0 = m0 + r;
            float vals[8];
            #pragma unroll
            for (int j = 0; j < 8; j++) {
                float2 v = upk2(acc[i][j]);
                float x = (half ? v.y : v.x) + bs[j];
                if (MODE == B_V) x = fmaxf(x, 0.f);
                vals[j] = x;
            }
            if (MODE == B_FINAL) {
                if (i0 < nact) {
                    int rm = g_rowmap[i0];
                    int b = rm & 127, ts = rm >> 7;
                    float* dst = Cp + ((size_t)(b * NSTEP + ts)) * N + nb;
                    if (nb + 7 < N) {
                        *(float4*)(dst)     = make_float4(vals[0], vals[1], vals[2], vals[3]);
                        *(float4*)(dst + 4) = make_float4(vals[4], vals[5], vals[6], vals[7]);
                    } else {
                        #pragma unroll
                        for (int j = 0; j < 8; j++)
                            if (nb + j < N) dst[j] = vals[j];
                    }
                }
            } else {
                float* dst = Cp + (size_t)i0 * ldc + nb;
                *(float4*)(dst)     = make_float4(vals[0], vals[1], vals[2], vals[3]);
                *(float4*)(dst + 4) = make_float4(vals[4], vals[5], vals[6], vals[7]);
            }
        }
    }
}

// ===========================================================================
// SMALL GEMM (split-K, 64x64, 8x4 microtile) — per-step latency-bound GEMMs
// ===========================================================================
enum { MODE_VG = 0, MODE_GSTEP = 2, MODE_HS = 3 };

template<int MODE, int KSPLIT>
__global__ __launch_bounds__(128)
void sgemm_nt(const float* __restrict__ A,     // external A (gimg)
              const float* __restrict__ Bm,    // B (N x ldb row-major)
              const float* __restrict__ B2,    // HS second B
              int N, int K, int t)             // K = per-split K
{
    __shared__ __align__(16) float As [2][16][68];
    __shared__ __align__(16) float Bsd[2][16][132];

    const int tid = threadIdx.x;
    const int n0  = blockIdx.x * 64;
    const int m0C = blockIdx.y * 64;
    const int kz  = blockIdx.z;
    int m0A = m0C;

    if (MODE == MODE_GSTEP) { if (m0C >= g_cnt[t]) return; }
    if (MODE == MODE_HS) {
        if (m0C >= 128) { Bm = B2; m0A = m0C - 128; }
        if (m0A >= g_cnt[t]) return;
    }
    if (MODE == MODE_GSTEP) Bm = g_Wpack + 1024;

    const int ldb = (MODE == MODE_GSTEP) ? 1536
                  : (MODE == MODE_VG ? ENCD : HD);

    const float* arow[2];
    int rowi[2], kci[2];
    #pragma unroll
    for (int it = 0; it < 2; it++) {
        int s   = tid + it * 128;
        int row = s >> 2;
        rowi[it] = row;
        kci [it] = (s & 3) << 2;
        int gm  = m0A + row;
        if (MODE == MODE_VG) {
            arow[it] = A + (size_t)g_sortind[gm] * ENCD + kz * K;
        } else if (MODE == MODE_GSTEP) {
            arow[it] = g_H + (size_t)gm * HD + kz * K;
        } else {
            arow[it] = ((m0C >= 128) ? g_S : g_HN) + (size_t)gm * HD + kz * K;
        }
    }
    const float* brow[2];
    int bn[2], bkci[2];
    bool bok[2];
    #pragma unroll
    for (int it = 0; it < 2; it++) {
        int s  = tid + it * 128;
        int nr = s >> 2;
        bn  [it] = nr;
        bkci[it] = (s & 3) << 2;
        int gn = n0 + nr;
        bok [it] = (gn < N);
        brow[it] = Bm + (size_t)(bok[it] ? gn : 0) * ldb + kz * K;
    }

    float4 aR[2], bR[2];

    #define LOAD_TILE(k0)                                                     \
        {                                                                     \
            _Pragma("unroll")                                                 \
            for (int it = 0; it < 2; it++)                                    \
                aR[it] = *(const float4*)&arow[it][(k0) + kci[it]];           \
            _Pragma("unroll")                                                 \
            for (int it = 0; it < 2; it++)                                    \
                bR[it] = bok[it] ? *(const float4*)&brow[it][(k0) + bkci[it]] \
                                 : make_float4(0.f, 0.f, 0.f, 0.f);           \
        }

    #define STORE_TILE(buf)                                                   \
        {                                                                     \
            _Pragma("unroll")                                                 \
            for (int it = 0; it < 2; it++) {                                  \
                int kc = kci[it], row = rowi[it];                             \
                As[buf][kc + 0][row] = aR[it].x;                              \
                As[buf][kc + 1][row] = aR[it].y;                              \
                As[buf][kc + 2][row] = aR[it].z;                              \
                As[buf][kc + 3][row] = aR[it].w;                              \
            }                                                                 \
            _Pragma("unroll")                                                 \
            for (int it = 0; it < 2; it++) {                                  \
                int kc = bkci[it], nr2 = bn[it] * 2;                          \
                *(float2*)&Bsd[buf][kc + 0][nr2] = make_float2(bR[it].x, bR[it].x); \
                *(float2*)&Bsd[buf][kc + 1][nr2] = make_float2(bR[it].y, bR[it].y); \
                *(float2*)&Bsd[buf][kc + 2][nr2] = make_float2(bR[it].z, bR[it].z); \
                *(float2*)&Bsd[buf][kc + 3][nr2] = make_float2(bR[it].w, bR[it].w); \
            }                                                                 \
        }

    #define LDFRAG(buf, k, aA, aB, b01, b23)                                  \
        {                                                                     \
            const ulonglong2* ap = (const ulonglong2*)&As[buf][k][ty << 3];   \
            aA = ap[0]; aB = ap[1];                                           \
            const ulonglong2* bp = (const ulonglong2*)&Bsd[buf][k][tx << 3];  \
            b01 = bp[0]; b23 = bp[1];                                         \
        }

    unsigned long long acc[4][4];
    #pragma unroll
    for (int i = 0; i < 4; i++)
        #pragma unroll
        for (int j = 0; j < 4; j++) acc[i][j] = 0ull;

    const int ty = tid >> 4;
    const int tx = tid & 15;

    LOAD_TILE(0);
    STORE_TILE(0);
    __syncthreads();
    int buf = 0;
    const int KT = K >> 4;
    for (int kt = 0; kt < KT; kt++) {
        if (kt + 1 < KT) LOAD_TILE((kt + 1) << 4);
        ulonglong2 aAc, aBc, b01c, b23c, aAn, aBn, b01n, b23n;
        LDFRAG(buf, 0, aAc, aBc, b01c, b23c);
        #pragma unroll
        for (int k = 0; k < 16; k++) {
            if (k < 15) LDFRAG(buf, k + 1, aAn, aBn, b01n, b23n);
            ffma2(acc[0][0], aAc.x, b01c.x); ffma2(acc[0][1], aAc.x, b01c.y);
            ffma2(acc[0][2], aAc.x, b23c.x); ffma2(acc[0][3], aAc.x, b23c.y);
            ffma2(acc[1][0], aAc.y, b01c.x); ffma2(acc[1][1], aAc.y, b01c.y);
            ffma2(acc[1][2], aAc.y, b23c.x); ffma2(acc[1][3], aAc.y, b23c.y);
            ffma2(acc[2][0], aBc.x, b01c.x); ffma2(acc[2][1], aBc.x, b01c.y);
            ffma2(acc[2][2], aBc.x, b23c.x); ffma2(acc[2][3], aBc.x, b23c.y);
            ffma2(acc[3][0], aBc.y, b01c.x); ffma2(acc[3][1], aBc.y, b01c.y);
            ffma2(acc[3][2], aBc.y, b23c.x); ffma2(acc[3][3], aBc.y, b23c.y);
            if (k < 15) { aAc = aAn; aBc = aBn; b01c = b01n; b23c = b23n; }
        }
        if (kt + 1 < KT) {
            STORE_TILE(buf ^ 1);
            __syncthreads();
            buf ^= 1;
        }
    }
    #undef LOAD_TILE
    #undef STORE_TILE
    #undef LDFRAG

    // ---- epilogue: split-K partials ----
    float* Cp;
    int ldc;
    if      (MODE == MODE_GSTEP) { Cp = g_Gp    + (size_t)kz * (BB * 2560);   ldc = 2560; }
    else if (MODE == MODE_HS)    { Cp = g_WhWsP + (size_t)kz * (2 * BB * HD); ldc = HD; }
    else                         { Cp = g_vgP   + (size_t)kz * (BB * HD);     ldc = HD; }

    #pragma unroll
    for (int j = 0; j < 4; j++) {
        int n = n0 + (tx << 2) + j;
        if (n >= N) continue;
        #pragma unroll
        for (int i2 = 0; i2 < 4; i2++) {
            float2 v = upk2(acc[i2][j]);
            int r0 = (ty << 3) + (i2 << 1);
            Cp[(size_t)(m0C + r0)     * ldc + n] = v.x;
            Cp[(size_t)(m0C + r0 + 1) * ldc + n] = v.y;
        }
    }
}

// ---------------------------------------------------------------------------
// Prep: stable descending argsort, caps gather, cnt_t, compact rowmap, tails
// ---------------------------------------------------------------------------
__global__ void prep_kernel(const int* __restrict__ caplens,
                            const int* __restrict__ caps,
                            float* __restrict__ out, long long out_size)
{
    __shared__ int clsh[BB];
    __shared__ int off[NSTEP + 1];
    int b = threadIdx.x;
    int cl = caplens[b];
    clsh[b] = cl;
    __syncthreads();
    int rank = 0;
    #pragma unroll 8
    for (int j = 0; j < BB; j++) {
        int cj = clsh[j];
        if (cj > cl || (cj == cl && j < b)) rank++;
    }
    g_sortind[rank] = b;
    g_declen[rank]  = cl - 1;
    __syncthreads();

    int si = g_sortind[b];
    for (int t = 0; t < TT; t++) g_capss[b * TT + t] = caps[si * TT + t];

    if (b < NSTEP) {
        int c = 0;
        for (int j = 0; j < BB; j++) if (g_declen[j] > b) c++;
        g_cnt[b] = c;
    }
    __syncthreads();
    if (b == 0) {
        int o = 0;
        for (int t = 0; t < NSTEP; t++) { off[t] = o; o += g_cnt[t]; }
        off[NSTEP] = o;
        g_nact = o;
    }
    __syncthreads();
    for (int t = 0; t < NSTEP; t++)
        if (b < g_cnt[t]) g_rowmap[off[t] + b] = t * BB + b;
    __syncthreads();
    int nact = off[NSTEP];
    int lastrm = g_rowmap[nact - 1];
    for (int i = nact + b; i < MACT_PAD; i += BB) g_rowmap[i] = lastrm;

    for (int i = b; i < BB * HD; i += BB) { g_H[i] = 0.f; g_M[i] = 0.f; }

    if (out_size >= PRED_ELEMS + 2816LL) {
        for (int t = 0; t < TT; t++)
            out[PRED_ELEMS + b * TT + t] = (float)g_capss[b * TT + t];
        out[PRED_ELEMS + 2560 + b] = (float)g_declen[b];
        out[PRED_ELEMS + 2688 + b] = (float)g_sortind[b];
    }
}

// ---------------------------------------------------------------------------
// Pack LSTM + gate weights into one (2560 x 1536) NT weight + fused bias
// ---------------------------------------------------------------------------
__global__ void pack_weights(const float* __restrict__ Wih, const float* __restrict__ Whh,
                             const float* __restrict__ Wx,  const float* __restrict__ Wph,
                             const float* __restrict__ bih, const float* __restrict__ bhh,
                             const float* __restrict__ bx,  const float* __restrict__ bph)
{
    int i = blockIdx.x * blockDim.x + threadIdx.x;
    int n = i / 1536;
    int k = i - n * 1536;
    float v;
    if (n < 2048) v = (k < 1024) ? Wih[n * 1024 + k] : Whh[n * 512 + (k - 1024)];
    else {
        int n2 = n - 2048;
        v = (k < 1024) ? Wx[n2 * 1024 + k] : Wph[n2 * 512 + (k - 1024)];
    }
    g_Wpack[i] = v;
    if (i < 2560)
        g_bpack[i] = (i < 2048) ? (bih[i] + bhh[i]) : (bx[i - 2048] + bph[i - 2048]);
}

// ---------------------------------------------------------------------------
// vg split-K reduction + bias + relu
// ---------------------------------------------------------------------------
__global__ void vg_reduce(const float* __restrict__ bg)
{
    int i = blockIdx.x * 256 + threadIdx.x;
    float v = bg[i & 511];
    #pragma unroll
    for (int z = 0; z < KS_VG; z++) v += g_vgP[z * (BB * HD) + i];
    g_vg[i] = fmaxf(v, 0.f);
}

// ---------------------------------------------------------------------------
// Zero-fill predictions of inactive (b,t) rows
// ---------------------------------------------------------------------------
__global__ void zero_inactive(float* __restrict__ out)
{
    int bt = blockIdx.x;
    int b = bt / NSTEP, t = bt - b * NSTEP;
    if (t < g_declen[b]) return;
    float4* dst = (float4*)(out + (size_t)bt * VOC);
    for (int i = threadIdx.x; i < VOC / 4; i += blockDim.x)
        dst[i] = make_float4(0.f, 0.f, 0.f, 0.f);
}

// ---------------------------------------------------------------------------
// LSTM elementwise (active rows only): sums split-K partials + GX
// ---------------------------------------------------------------------------
__device__ __forceinline__ float sigm(float x) { return 1.0f / (1.0f + expf(-x)); }

__global__ void lstm_ew(int t)
{
    if ((int)(blockIdx.x >> 1) >= g_cnt[t]) return;
    int idx = blockIdx.x * 256 + threadIdx.x;
    int b = idx >> 9, j = idx & 511;
    const float* GX = g_GX + ((size_t)b * NSTEP + t) * 2560;
    float ga[5];
    #pragma unroll
    for (int g5 = 0; g5 < 5; g5++) {
        int n = g5 * 512 + j;
        float v = GX[n];
        #pragma unroll
        for (int z = 0; z < KS_G; z++)
            v += g_Gp[(size_t)z * (BB * 2560) + (size_t)b * 2560 + n];
        ga[g5] = v;
    }
    float ig = sigm(ga[0]);
    float fg = sigm(ga[1]);
    float gg = tanhf(ga[2]);
    float og = sigm(ga[3]);
    float gt = sigm(ga[4]);
    float mn = fg * g_M[idx] + ig * gg;
    float tm = tanhf(mn);
    float hn = og * tm;
    g_HN[idx] = hn;
    g_S[idx]  = gt * tm;
    if (t < g_declen[b]) { g_H[idx] = hn; g_M[idx] = mn; }
}

// ---------------------------------------------------------------------------
// Fused attention per t (active rows only): sums HS split-K partials + biases
// ---------------------------------------------------------------------------
__global__ __launch_bounds__(512)
void attn_fused(int t,
                const float* __restrict__ attbh, const float* __restrict__ attbs,
                const float* __restrict__ wa,    const float* __restrict__ ba,
                const float* __restrict__ wahat, const float* __restrict__ bahat)
{
    int b = blockIdx.x;
    if (b >= g_cnt[t]) return;
    __shared__ float shWh[512];
    __shared__ float shWs[512];
    __shared__ float zsh[64];
    __shared__ float alph[64];
    __shared__ float betash;
    int tid = threadIdx.x;
    {
        float vh = attbh[tid], vs = attbs[tid];
        #pragma unroll
        for (int z = 0; z < KS_HS; z++) {
            vh += g_WhWsP[(size_t)z * (2 * BB * HD) + (size_t)b * HD + tid];
            vs += g_WhWsP[(size_t)z * (2 * BB * HD) + (size_t)(BB + b) * HD + tid];
        }
        shWh[tid] = vh;
        shWs[tid] = vs;
    }
    __syncthreads();

    int warp = tid >> 5, lane = tid & 31;
    for (int idx = warp; idx < 50; idx += 16) {
        float sum = 0.f;
        if (idx < 49) {
            const float* wv = g_WV + ((size_t)(b * PP + idx)) * 512;
            #pragma unroll
            for (int e = lane; e < 512; e += 32)
                sum += tanhf(wv[e] + shWh[e]) * wa[e];
        } else {
            #pragma unroll
            for (int e = lane; e < 512; e += 32)
                sum += tanhf(shWs[e] + shWh[e]) * wahat[e];
        }
        #pragma unroll
        for (int o = 16; o; o >>= 1) sum += __shfl_down_sync(0xffffffffu, sum, o);
        if (lane == 0) zsh[idx] = sum + (idx < 49 ? ba[0] : bahat[0]);
    }
    __syncthreads();

    if (warp == 0) {
        float z0 = (lane < 49)      ? zsh[lane]      : -1e30f;
        float z1 = (lane + 32 < 49) ? zsh[lane + 32] : -1e30f;
        float mx = fmaxf(z0, z1);
        #pragma unroll
        for (int o = 16; o; o >>= 1) mx = fmaxf(mx, __shfl_xor_sync(0xffffffffu, mx, o));
        float e0 = (lane < 49)      ? expf(z0 - mx) : 0.f;
        float e1 = (lane + 32 < 49) ? expf(z1 - mx) : 0.f;
        float sm = e0 + e1;
        #pragma unroll
        for (int o = 16; o; o >>= 1) sm += __shfl_xor_sync(0xffffffffu, sm, o);
        float inv = 1.f / sm;
        if (lane < 49)      alph[lane]      = e0 * inv;
        if (lane + 32 < 49) alph[lane + 32] = e1 * inv;
        if (lane == 0) {
            float zh = zsh[49];
            float m2 = fmaxf(mx, zh);
            float s2 = sm * expf(mx - m2) + expf(zh - m2);
            betash = expf(zh - m2) / s2;
        }
    }
    __syncthreads();

    float beta = betash;
    float c = 0.f;
    const float* Vb = g_V + (size_t)b * PP * 512 + tid;
    #pragma unroll 7
    for (int p = 0; p < PP; p++) c += alph[p] * Vb[p * 512];
    int idx = b * 512 + tid;
    float ch = beta * g_S[idx] + (1.f - beta) * c + g_HN[idx];
    g_CH[((size_t)t * BB + b) * 512 + tid] = ch;
}

// ---------------------------------------------------------------------------
// Host launcher — kernel launches only
// ---------------------------------------------------------------------------
extern "C" void kernel_launch(void* const* d_in, const int* in_sizes, int n_in,
                              void* d_out, int out_size)
{
    (void)in_sizes; (void)n_in;
    const float* enc    = (const float*)d_in[0];
    const float* gimg   = (const float*)d_in[1];
    const int*   caps   = (const int*)  d_in[2];
    const int*   caplens= (const int*)  d_in[3];
    const float* embW   = (const float*)d_in[4];
    const float* Wih    = (const float*)d_in[5];
    const float* Whh    = (const float*)d_in[6];
    const float* bih    = (const float*)d_in[7];
    const float* bhh    = (const float*)d_in[8];
    const float* Wg     = (const float*)d_in[9];
    const float* bg     = (const float*)d_in[10];
    const float* Wi     = (const float*)d_in[11];
    const float* bi     = (const float*)d_in[12];
    const float* Wx     = (const float*)d_in[13];
    const float* bx     = (const float*)d_in[14];
    const float* Wph    = (const float*)d_in[15];
    const float* bph    = (const float*)d_in[16];
    const float* attWh  = (const float*)d_in[17];
    const float* attbh  = (const float*)d_in[18];
    const float* attWs  = (const float*)d_in[19];
    const float* attbs  = (const float*)d_in[20];
    const float* attWV  = (const float*)d_in[21];
    const float* attbV  = (const float*)d_in[22];
    const float* wa     = (const float*)d_in[23];
    const float* ba     = (const float*)d_in[24];
    const float* wahat  = (const float*)d_in[25];
    const float* bahat  = (const float*)d_in[26];
    const float* finalW = (const float*)d_in[27];
    const float* finalb = (const float*)d_in[28];
    float* out = (float*)d_out;

    // --- setup ---
    prep_kernel<<<1, 128>>>(caplens, caps, out, (long long)out_size);
    pack_weights<<<(2560 * 1536) / 256, 256>>>(Wih, Whh, Wx, Wph, bih, bhh, bx, bph);
    zero_inactive<<<BB * NSTEP, 256>>>(out);

    // vg partials: gimg_s @ Wg^T   (split-K 8, K=256 each)
    sgemm_nt<MODE_VG, KS_VG><<<dim3(8, 2, KS_VG), 128>>>(gimg, Wg, nullptr,
        HD, ENCD / KS_VG, 0);
    vg_reduce<<<BB * HD / 256, 256>>>(bg);
    // V = relu(enc_s @ Wi^T + bi)
    sgemm_big<B_V><<<dim3(8, MROWS / 128), 128>>>(enc, Wi, bi, nullptr, HD, ENCD);
    // GX = [emb_t | vg] @ Wpack[:, :1024]^T + bpack   (all t)
    sgemm_big<B_GXB><<<dim3(40, MACT_PAD / 128), 128>>>(embW, nullptr, nullptr,
        nullptr, 2560, 1024);
    // WV = V @ att_WV^T + bV
    sgemm_big<B_WV><<<dim3(8, MROWS / 128), 128>>>(nullptr, attWV, attbV,
        nullptr, HD, HD);

    // --- 19 sequential decode steps ---
    for (int t = 0; t < NSTEP; t++) {
        sgemm_nt<MODE_GSTEP, KS_G><<<dim3(40, 2, KS_G), 128>>>(nullptr, nullptr, nullptr,
            2560, HD / KS_G, t);
        lstm_ew<<<BB * HD / 256, 256>>>(t);
        sgemm_nt<MODE_HS, KS_HS><<<dim3(8, 4, KS_HS), 128>>>(nullptr, attWh, attWs,
            HD, HD / KS_HS, t);
        attn_fused<<<BB, 512>>>(t, attbh, attbs, wa, ba, wahat, bahat);
    }

    // --- batched final projection over compacted active rows ---
    sgemm_big<B_FINAL><<<dim3((VOC + 63) / 64, MACT_PAD / 128), 128>>>(nullptr,
        finalW, finalb, out, VOC, HD);
}